// round 3
// baseline (speedup 1.0000x reference)
#include <cuda_runtime.h>
#include <cuda_bf16.h>
#include <cstdint>
#include <cstdio>

#define N_DRUG 200000
#define N_DIS  100000
#define HDIM   128
#define NE     600000
#define NB     8192

#define C_DIS_S0  0
#define C_DIS_S1  1
#define C_DIS_AG  2
#define C_DRUG_S0 3
#define C_DRUG_S1 4
#define C_DRUG_AG 5

// ---------------- device scratch (no allocations allowed) ----------------
__device__ float g_agg_dis [(size_t)N_DIS  * HDIM];
__device__ float g_agg_drug[(size_t)N_DRUG * HDIM];
__device__ int   g_cnt_dis [N_DIS];
__device__ int   g_cnt_drug[N_DRUG];
__device__ float g_dis_L1_0 [(size_t)N_DIS  * HDIM];
__device__ float g_dis_L1_1 [(size_t)N_DIS  * HDIM];
__device__ float g_drug_L1_0[(size_t)N_DRUG * HDIM];
__device__ float g_drug_L1_1[(size_t)N_DRUG * HDIM];
__device__ float g_drug_L2 [(size_t)N_DRUG * HDIM];
__device__ float g_dis_L2  [(size_t)N_DIS  * HDIM];
__device__ int g_m_dis_s0[N_DIS],  g_m_dis_s1[N_DIS],  g_m_dis_ag[N_DIS];
__device__ int g_m_drug_s0[N_DRUG],g_m_drug_s1[N_DRUG],g_m_drug_ag[N_DRUG];
__device__ int g_l_dis_s0[N_DIS],  g_l_dis_s1[N_DIS],  g_l_dis_ag[N_DIS];
__device__ int g_l_drug_s0[N_DRUG],g_l_drug_s1[N_DRUG],g_l_drug_ag[N_DRUG];
__device__ int g_ctr[8];
__device__ float g_A0[HDIM*HDIM], g_A1[HDIM*HDIM], g_c0[HDIM], g_c1[HDIM];
__device__ float g_Md[256*HDIM], g_Ms[256*HDIM], g_btil[256];
__device__ float g_H1[(size_t)NB * 256];
__device__ float g_H2[(size_t)NB * HDIM];

// ---------------- init: zero masks / counters / degree counts ----------------
__global__ __launch_bounds__(256) void k_init()
{
    int i = blockIdx.x * blockDim.x + threadIdx.x;
    if (i < N_DIS) {
        g_m_dis_s0[i] = 0; g_m_dis_s1[i] = 0; g_m_dis_ag[i] = 0; g_cnt_dis[i] = 0;
    }
    if (i < N_DRUG) {
        g_m_drug_s0[i] = 0; g_m_drug_s1[i] = 0; g_m_drug_ag[i] = 0; g_cnt_drug[i] = 0;
    }
    if (i < 8) g_ctr[i] = 0;
}

// mark target nodes (drug_idx -> drug_s0, disease_idx -> dis_s1) + agg unions
__global__ __launch_bounds__(256) void k_mark(const int* __restrict__ drug_idx,
                                              const int* __restrict__ disease_idx)
{
    int i = blockIdx.x * blockDim.x + threadIdx.x;
    if (i >= NB) return;
    int d = drug_idx[i];
    if (atomicExch(&g_m_drug_s0[d], 1) == 0) g_l_drug_s0[atomicAdd(&g_ctr[C_DRUG_S0], 1)] = d;
    if (atomicExch(&g_m_drug_ag[d], 1) == 0) g_l_drug_ag[atomicAdd(&g_ctr[C_DRUG_AG], 1)] = d;
    int s = disease_idx[i];
    if (atomicExch(&g_m_dis_s1[s], 1) == 0) g_l_dis_s1[atomicAdd(&g_ctr[C_DIS_S1], 1)] = s;
    if (atomicExch(&g_m_dis_ag[s], 1) == 0) g_l_dis_ag[atomicAdd(&g_ctr[C_DIS_AG], 1)] = s;
}

// di2dr edges: in-degree of drugs; srcs (dis) feeding selected drugs -> dis_s0
__global__ __launch_bounds__(256) void k_scanA(const int* __restrict__ src, const int* __restrict__ dst)
{
    int e = blockIdx.x * blockDim.x + threadIdx.x;
    if (e >= NE) return;
    int d = dst[e];
    atomicAdd(&g_cnt_drug[d], 1);
    if (g_m_drug_s0[d]) {
        int s = src[e];
        if (atomicExch(&g_m_dis_s0[s], 1) == 0) g_l_dis_s0[atomicAdd(&g_ctr[C_DIS_S0], 1)] = s;
        if (atomicExch(&g_m_dis_ag[s], 1) == 0) g_l_dis_ag[atomicAdd(&g_ctr[C_DIS_AG], 1)] = s;
    }
}

// d2di edges: in-degree of diseases; srcs (drug) feeding selected diseases -> drug_s1
__global__ __launch_bounds__(256) void k_scanB(const int* __restrict__ src, const int* __restrict__ dst)
{
    int e = blockIdx.x * blockDim.x + threadIdx.x;
    if (e >= NE) return;
    int d = dst[e];
    atomicAdd(&g_cnt_dis[d], 1);
    if (g_m_dis_s1[d]) {
        int s = src[e];
        if (atomicExch(&g_m_drug_s1[s], 1) == 0) g_l_drug_s1[atomicAdd(&g_ctr[C_DRUG_S1], 1)] = s;
        if (atomicExch(&g_m_drug_ag[s], 1) == 0) g_l_drug_ag[atomicAdd(&g_ctr[C_DRUG_AG], 1)] = s;
    }
}

// zero 128-float rows listed in `list` (count at *cntp). one warp per row
__global__ __launch_bounds__(256) void k_zero_rows(float* __restrict__ X,
                                                   const int* __restrict__ list,
                                                   const int* __restrict__ cntp)
{
    int w = (blockIdx.x * blockDim.x + threadIdx.x) >> 5;
    int lane = threadIdx.x & 31;
    if (w >= *cntp) return;
    int node = list[w];
    ((float4*)(X + (size_t)node * HDIM))[lane] = make_float4(0.f, 0.f, 0.f, 0.f);
}

// segment sum: for each edge with masked dst, agg[dst] += X[src]. one warp per edge
__global__ __launch_bounds__(256) void k_agg(const int* __restrict__ src,
                                             const int* __restrict__ dst,
                                             const float* __restrict__ X,
                                             const int* __restrict__ mask,
                                             float* __restrict__ agg)
{
    int w = (blockIdx.x * blockDim.x + threadIdx.x) >> 5;
    int lane = threadIdx.x & 31;
    if (w >= NE) return;
    int d = __ldg(dst + w);
    if (!mask[d]) return;
    int s = __ldg(src + w);
    float4 v = ((const float4*)(X + (size_t)s * HDIM))[lane];
    float* p = agg + (size_t)d * HDIM + lane * 4;
    atomicAdd(p + 0, v.x);
    atomicAdd(p + 1, v.y);
    atomicAdd(p + 2, v.z);
    atomicAdd(p + 3, v.w);
}

// ---------------- tiled SGEMM over (possibly gathered/masked) rows ----------------
// out[row, n0+n] = act( sum_{k<K1} (X1[a1,k]*sc) * Wa[n0+n,k]
//                     + sum_{k>=K1} X2[a2,k-K1] * Wb[n0+n,k-K1] + bias[n0+n] )
#define TMR 64
#define KCH 32
__global__ __launch_bounds__(256) void k_gemm(
    const int* __restrict__ rowlist, const int* __restrict__ rowcnt, int nfixed,
    const float* __restrict__ X1, const int* __restrict__ g1, const int* __restrict__ cnt1,
    const float* __restrict__ X2, const int* __restrict__ g2,
    int K1, int K,
    const float* __restrict__ Wa, const float* __restrict__ Wb,
    const float* __restrict__ bias,
    float* __restrict__ out, int Nout, int out_by_node, int relu)
{
    __shared__ float As[TMR][KCH + 1];
    __shared__ float Ws[KCH][128];
    __shared__ int   s_a1[TMR], s_a2[TMR], s_or[TMR];
    __shared__ float s_sc[TMR];

    int nr = rowcnt ? *rowcnt : nfixed;
    int row0 = blockIdx.x * TMR;
    if (row0 >= nr) return;
    int t = threadIdx.x;
    int n0 = blockIdx.y * 128;

    if (t < TMR) {
        int r = row0 + t;
        int a1 = 0, a2 = 0, orow = -1; float sc = 1.f;
        if (r < nr) {
            int node = rowlist ? rowlist[r] : r;
            a1 = g1 ? g1[r] : node;
            a2 = g2 ? g2[r] : node;
            orow = out_by_node ? node : r;
            if (cnt1) { int c = cnt1[a1]; sc = 1.f / (float)(c > 1 ? c : 1); }
        }
        s_a1[t] = a1; s_a2[t] = a2; s_or[t] = orow; s_sc[t] = sc;
    }
    __syncthreads();

    float acc[4][8];
#pragma unroll
    for (int i = 0; i < 4; ++i)
#pragma unroll
        for (int j = 0; j < 8; ++j) acc[i][j] = 0.f;

    int tx = t & 15;
    int ty = t >> 4;
    int K2 = K - K1;
    int nch = K / KCH;

    for (int c = 0; c < nch; ++c) {
        int kb = c * KCH;
        {   // A tile: thread loads 8 consecutive k of one row
            int i  = t >> 2;
            int k0 = (t & 3) * 8;
            float4 v0 = make_float4(0.f, 0.f, 0.f, 0.f), v1 = v0;
            if (s_or[i] >= 0) {
                int k = kb + k0;
                if (k < K1) {
                    const float4* p = (const float4*)(X1 + (size_t)s_a1[i] * K1 + k);
                    v0 = p[0]; v1 = p[1];
                    float sc = s_sc[i];
                    v0.x *= sc; v0.y *= sc; v0.z *= sc; v0.w *= sc;
                    v1.x *= sc; v1.y *= sc; v1.z *= sc; v1.w *= sc;
                } else {
                    const float4* p = (const float4*)(X2 + (size_t)s_a2[i] * K2 + (k - K1));
                    v0 = p[0]; v1 = p[1];
                }
            }
            As[i][k0+0] = v0.x; As[i][k0+1] = v0.y; As[i][k0+2] = v0.z; As[i][k0+3] = v0.w;
            As[i][k0+4] = v1.x; As[i][k0+5] = v1.y; As[i][k0+6] = v1.z; As[i][k0+7] = v1.w;
        }
        {   // W tile: thread loads 16 consecutive k of one output row
            int n  = t >> 1;
            int k0 = (t & 1) * 16;
            int gk = kb + k0;
            const float* wp = (gk < K1) ? (Wa + (size_t)(n0 + n) * K1 + gk)
                                        : (Wb + (size_t)(n0 + n) * K2 + (gk - K1));
#pragma unroll
            for (int j = 0; j < 16; j += 4) {
                float4 w = *(const float4*)(wp + j);
                Ws[k0+j+0][n] = w.x; Ws[k0+j+1][n] = w.y;
                Ws[k0+j+2][n] = w.z; Ws[k0+j+3][n] = w.w;
            }
        }
        __syncthreads();
#pragma unroll
        for (int kk = 0; kk < KCH; ++kk) {
            float4 w0 = *(const float4*)&Ws[kk][tx * 8];
            float4 w1 = *(const float4*)&Ws[kk][tx * 8 + 4];
#pragma unroll
            for (int i = 0; i < 4; ++i) {
                float a = As[ty * 4 + i][kk];
                acc[i][0] += a * w0.x; acc[i][1] += a * w0.y;
                acc[i][2] += a * w0.z; acc[i][3] += a * w0.w;
                acc[i][4] += a * w1.x; acc[i][5] += a * w1.y;
                acc[i][6] += a * w1.z; acc[i][7] += a * w1.w;
            }
        }
        __syncthreads();
    }

    float b[8];
#pragma unroll
    for (int j = 0; j < 8; ++j) b[j] = bias[n0 + tx * 8 + j];
#pragma unroll
    for (int i = 0; i < 4; ++i) {
        int ri = ty * 4 + i;
        if (s_or[ri] < 0) continue;
        float* op = out + (size_t)s_or[ri] * Nout + n0 + tx * 8;
        float4 o0, o1;
        o0.x = acc[i][0] + b[0]; o0.y = acc[i][1] + b[1];
        o0.z = acc[i][2] + b[2]; o0.w = acc[i][3] + b[3];
        o1.x = acc[i][4] + b[4]; o1.y = acc[i][5] + b[5];
        o1.z = acc[i][6] + b[6]; o1.w = acc[i][7] + b[7];
        if (relu) {
            o0.x = fmaxf(o0.x, 0.f); o0.y = fmaxf(o0.y, 0.f);
            o0.z = fmaxf(o0.z, 0.f); o0.w = fmaxf(o0.w, 0.f);
            o1.x = fmaxf(o1.x, 0.f); o1.y = fmaxf(o1.y, 0.f);
            o1.z = fmaxf(o1.z, 0.f); o1.w = fmaxf(o1.w, 0.f);
        }
        ((float4*)op)[0] = o0;
        ((float4*)op)[1] = o1;
    }
}

// fold attention (len-1 kv => softmax == 1): A_m = Wout_m @ Wv_m, c_m = Wout_m@bv_m + bout_m
__global__ __launch_bounds__(128) void k_fold1(const float* __restrict__ Win,
                                               const float* __restrict__ bin,
                                               const float* __restrict__ Wout,
                                               const float* __restrict__ bout)
{
    int m = blockIdx.y;
    int tt = blockIdx.x;
    int j = threadIdx.x;
    const float* Wv = Win + (size_t)m * 384 * 128 + 256 * 128;
    const float* Wo = Wout + (size_t)m * 128 * 128;
    const float* bv = bin + m * 384 + 256;
    const float* bo = bout + m * 128;
    const float* worow = Wo + (size_t)tt * 128;
    float s = 0.f;
    for (int u = 0; u < 128; ++u) s += worow[u] * Wv[(size_t)u * 128 + j];
    (m == 0 ? g_A0 : g_A1)[tt * 128 + j] = s;
    __shared__ float red[128];
    red[j] = worow[j] * bv[j];
    __syncthreads();
    for (int o = 64; o > 0; o >>= 1) { if (j < o) red[j] += red[j + o]; __syncthreads(); }
    if (j == 0) (m == 0 ? g_c0 : g_c1)[tt] = red[0] + bo[tt];
}

// fold the attention affine maps into mlp_W1:
// h1 = relu(Md*de + Ms*se + btil)
__global__ __launch_bounds__(128) void k_fold2(const float* __restrict__ W1,
                                               const float* __restrict__ b1)
{
    int o = blockIdx.x, j = threadIdx.x;
    const float* wrow = W1 + (size_t)o * 512;
    float md = wrow[j];
    float ms = wrow[128 + j];
    for (int tt = 0; tt < 128; ++tt) {
        ms += wrow[256 + tt] * g_A0[tt * 128 + j];   // drug_att = A0*se + c0
        md += wrow[384 + tt] * g_A1[tt * 128 + j];   // dis_att  = A1*de + c1
    }
    g_Md[o * 128 + j] = md;
    g_Ms[o * 128 + j] = ms;
    __shared__ float red[128];
    red[j] = wrow[256 + j] * g_c0[j] + wrow[384 + j] * g_c1[j];
    __syncthreads();
    for (int t2 = 64; t2 > 0; t2 >>= 1) { if (j < t2) red[j] += red[j + t2]; __syncthreads(); }
    if (j == 0) g_btil[o] = red[0] + b1[o];
}

// final: out[i] = H2[i] . W3 + b3
__global__ __launch_bounds__(256) void k_dot(const float* __restrict__ H2,
                                             const float* __restrict__ W3,
                                             const float* __restrict__ b3,
                                             float* __restrict__ out)
{
    int w = (blockIdx.x * blockDim.x + threadIdx.x) >> 5;
    int lane = threadIdx.x & 31;
    if (w >= NB) return;
    float4 h = ((const float4*)(H2 + (size_t)w * 128))[lane];
    float4 c = ((const float4*)W3)[lane];
    float s = h.x * c.x + h.y * c.y + h.z * c.z + h.w * c.w;
    for (int o = 16; o; o >>= 1) s += __shfl_xor_sync(0xffffffffu, s, o);
    if (lane == 0) out[w] = s + b3[0];
}

// ---------------- host ----------------
static inline int ceildiv(int a, int b) { return (a + b - 1) / b; }

extern "C" void kernel_launch(void* const* d_in, const int* in_sizes, int n_in,
                              void* d_out, int out_size)
{
    // input layout auto-detect: ints-first (dict order) vs floats-first
    int fi, ii;
    if (in_sizes[0] == NE) { ii = 0; fi = 6; } else { fi = 0; ii = 15; }
    const float* emb_drug  = (const float*)d_in[fi + 0];
    const float* emb_dis   = (const float*)d_in[fi + 1];
    const float* conv_Wl   = (const float*)d_in[fi + 2];
    const float* conv_bl   = (const float*)d_in[fi + 3];
    const float* conv_Wr   = (const float*)d_in[fi + 4];
    const float* attn_Win  = (const float*)d_in[fi + 5];
    const float* attn_bin  = (const float*)d_in[fi + 6];
    const float* attn_Wout = (const float*)d_in[fi + 7];
    const float* attn_bout = (const float*)d_in[fi + 8];
    const float* mlp_W1    = (const float*)d_in[fi + 9];
    const float* mlp_b1    = (const float*)d_in[fi + 10];
    const float* mlp_W2    = (const float*)d_in[fi + 11];
    const float* mlp_b2    = (const float*)d_in[fi + 12];
    const float* mlp_W3    = (const float*)d_in[fi + 13];
    const float* mlp_b3    = (const float*)d_in[fi + 14];
    const int* src_d2di    = (const int*)d_in[ii + 0];
    const int* dst_d2di    = (const int*)d_in[ii + 1];
    const int* src_di2dr   = (const int*)d_in[ii + 2];
    const int* dst_di2dr   = (const int*)d_in[ii + 3];
    const int* drug_idx    = (const int*)d_in[ii + 4];
    const int* disease_idx = (const int*)d_in[ii + 5];
    float* out = (float*)d_out;

    // device addresses of scratch symbols
    void* p;
    cudaGetSymbolAddress(&p, g_agg_dis);    float* agg_dis   = (float*)p;
    cudaGetSymbolAddress(&p, g_agg_drug);   float* agg_drug  = (float*)p;
    cudaGetSymbolAddress(&p, g_cnt_dis);    int*   cnt_dis   = (int*)p;
    cudaGetSymbolAddress(&p, g_cnt_drug);   int*   cnt_drug  = (int*)p;
    cudaGetSymbolAddress(&p, g_dis_L1_0);   float* dis_L1_0  = (float*)p;
    cudaGetSymbolAddress(&p, g_dis_L1_1);   float* dis_L1_1  = (float*)p;
    cudaGetSymbolAddress(&p, g_drug_L1_0);  float* drug_L1_0 = (float*)p;
    cudaGetSymbolAddress(&p, g_drug_L1_1);  float* drug_L1_1 = (float*)p;
    cudaGetSymbolAddress(&p, g_drug_L2);    float* drug_L2   = (float*)p;
    cudaGetSymbolAddress(&p, g_dis_L2);     float* dis_L2    = (float*)p;
    cudaGetSymbolAddress(&p, g_m_dis_s0);   int* m_dis_s0    = (int*)p;
    cudaGetSymbolAddress(&p, g_m_dis_s1);   int* m_dis_s1    = (int*)p;
    cudaGetSymbolAddress(&p, g_m_dis_ag);   int* m_dis_ag    = (int*)p;
    cudaGetSymbolAddress(&p, g_m_drug_s0);  int* m_drug_s0   = (int*)p;
    cudaGetSymbolAddress(&p, g_m_drug_ag);  int* m_drug_ag   = (int*)p;
    cudaGetSymbolAddress(&p, g_l_dis_s0);   int* l_dis_s0    = (int*)p;
    cudaGetSymbolAddress(&p, g_l_dis_s1);   int* l_dis_s1    = (int*)p;
    cudaGetSymbolAddress(&p, g_l_dis_ag);   int* l_dis_ag    = (int*)p;
    cudaGetSymbolAddress(&p, g_l_drug_s0);  int* l_drug_s0   = (int*)p;
    cudaGetSymbolAddress(&p, g_l_drug_s1);  int* l_drug_s1   = (int*)p;
    cudaGetSymbolAddress(&p, g_l_drug_ag);  int* l_drug_ag   = (int*)p;
    cudaGetSymbolAddress(&p, g_ctr);        int* ctr         = (int*)p;
    cudaGetSymbolAddress(&p, g_Md);         float* Md        = (float*)p;
    cudaGetSymbolAddress(&p, g_Ms);         float* Ms        = (float*)p;
    cudaGetSymbolAddress(&p, g_btil);       float* btil      = (float*)p;
    cudaGetSymbolAddress(&p, g_H1);         float* H1        = (float*)p;
    cudaGetSymbolAddress(&p, g_H2);         float* H2        = (float*)p;

    auto woff = [](int s, int l, int et) { return (size_t)((s * 2 + l) * 2 + et) * 128 * 128; };
    auto boff = [](int s, int l, int et) { return (size_t)((s * 2 + l) * 2 + et) * 128; };

    // 1. init masks/counters/degrees
    k_init<<<ceildiv(N_DRUG, 256), 256>>>();
    // 2. mark targets, 3. edge scans (degrees + 1-hop frontier)
    k_mark<<<ceildiv(NB, 256), 256>>>(drug_idx, disease_idx);
    k_scanA<<<ceildiv(NE, 256), 256>>>(src_di2dr, dst_di2dr);
    k_scanB<<<ceildiv(NE, 256), 256>>>(src_d2di, dst_d2di);
    // 4. zero L1 agg rows (union lists), then aggregate layer-0 embeddings
    k_zero_rows<<<ceildiv(N_DIS, 8), 256>>>(agg_dis, l_dis_ag, ctr + C_DIS_AG);
    k_zero_rows<<<ceildiv(N_DRUG, 8), 256>>>(agg_drug, l_drug_ag, ctr + C_DRUG_AG);
    k_agg<<<ceildiv(NE, 8), 256>>>(src_d2di, dst_d2di, emb_drug, m_dis_ag, agg_dis);
    k_agg<<<ceildiv(NE, 8), 256>>>(src_di2dr, dst_di2dr, emb_dis, m_drug_ag, agg_drug);
    // 5. L1 GEMMs (masked rows): out = relu(mean_agg@Wl^T + bl + x@Wr^T)
    dim3 gD(ceildiv(N_DIS, TMR), 1), gR(ceildiv(N_DRUG, TMR), 1);
    k_gemm<<<gD, 256>>>(l_dis_s0, ctr + C_DIS_S0, 0, agg_dis, nullptr, cnt_dis,
                        emb_dis, nullptr, 128, 256,
                        conv_Wl + woff(0,0,0), conv_Wr + woff(0,0,0), conv_bl + boff(0,0,0),
                        dis_L1_0, 128, 1, 1);
    k_gemm<<<gD, 256>>>(l_dis_s1, ctr + C_DIS_S1, 0, agg_dis, nullptr, cnt_dis,
                        emb_dis, nullptr, 128, 256,
                        conv_Wl + woff(1,0,0), conv_Wr + woff(1,0,0), conv_bl + boff(1,0,0),
                        dis_L1_1, 128, 1, 1);
    k_gemm<<<gR, 256>>>(l_drug_s0, ctr + C_DRUG_S0, 0, agg_drug, nullptr, cnt_drug,
                        emb_drug, nullptr, 128, 256,
                        conv_Wl + woff(0,0,1), conv_Wr + woff(0,0,1), conv_bl + boff(0,0,1),
                        drug_L1_0, 128, 1, 1);
    k_gemm<<<gR, 256>>>(l_drug_s1, ctr + C_DRUG_S1, 0, agg_drug, nullptr, cnt_drug,
                        emb_drug, nullptr, 128, 256,
                        conv_Wl + woff(1,0,1), conv_Wr + woff(1,0,1), conv_bl + boff(1,0,1),
                        drug_L1_1, 128, 1, 1);
    // 6. reuse agg buffers for L2: zero target rows, aggregate L1 features
    k_zero_rows<<<ceildiv(NB, 8), 256>>>(agg_drug, l_drug_s0, ctr + C_DRUG_S0);
    k_zero_rows<<<ceildiv(NB, 8), 256>>>(agg_dis, l_dis_s1, ctr + C_DIS_S1);
    k_agg<<<ceildiv(NE, 8), 256>>>(src_di2dr, dst_di2dr, dis_L1_0, m_drug_s0, agg_drug);
    k_agg<<<ceildiv(NE, 8), 256>>>(src_d2di, dst_d2di, drug_L1_1, m_dis_s1, agg_dis);
    // 7. L2 GEMMs (only target nodes)
    dim3 gT(ceildiv(NB, TMR), 1);
    k_gemm<<<gT, 256>>>(l_drug_s0, ctr + C_DRUG_S0, 0, agg_drug, nullptr, cnt_drug,
                        drug_L1_0, nullptr, 128, 256,
                        conv_Wl + woff(0,1,1), conv_Wr + woff(0,1,1), conv_bl + boff(0,1,1),
                        drug_L2, 128, 1, 1);
    k_gemm<<<gT, 256>>>(l_dis_s1, ctr + C_DIS_S1, 0, agg_dis, nullptr, cnt_dis,
                        dis_L1_1, nullptr, 128, 256,
                        conv_Wl + woff(1,1,0), conv_Wr + woff(1,1,0), conv_bl + boff(1,1,0),
                        dis_L2, 128, 1, 1);
    // 8. fold degenerate MHA into MLP layer 1
    k_fold1<<<dim3(128, 2), 128>>>(attn_Win, attn_bin, attn_Wout, attn_bout);
    k_fold2<<<256, 128>>>(mlp_W1, mlp_b1);
    // 9. pair head: h1 = relu(Md*de + Ms*se + btil); h2 = relu(W2*h1 + b2); out = W3.h2 + b3
    k_gemm<<<dim3(ceildiv(NB, TMR), 2), 256>>>(nullptr, nullptr, NB,
                        drug_L2, drug_idx, nullptr, dis_L2, disease_idx,
                        128, 256, Md, Ms, btil, H1, 256, 0, 1);
    k_gemm<<<dim3(ceildiv(NB, TMR), 1), 256>>>(nullptr, nullptr, NB,
                        H1, nullptr, nullptr, H1 /*unused*/, nullptr,
                        256, 256, mlp_W2, mlp_W2 /*unused*/, mlp_b2, H2, 128, 0, 1);
    k_dot<<<ceildiv(NB, 8), 256>>>(H2, mlp_W3, mlp_b3, out);
}

// round 4
// speedup vs baseline: 1.3784x; 1.3784x over previous
#include <cuda_runtime.h>
#include <cuda_bf16.h>
#include <cstdint>

#define N_DRUG 200000
#define N_DIS  100000
#define HDIM   128
#define NE     600000
#define NB     8192

#define C_DIS_S0  0
#define C_DIS_S1  1
#define C_DIS_AG  2
#define C_DRUG_S0 3
#define C_DRUG_S1 4
#define C_DRUG_AG 5

#define PSB 256
#define PST 256

// ---------------- device scratch ----------------
__device__ float g_aggc_dis [(size_t)N_DIS  * HDIM];   // L1 agg compact (ag-list order); reused for L2 dis agg
__device__ float g_aggc_drug[(size_t)N_DRUG * HDIM];   // same for drugs; reused for L2 drug agg
__device__ int   g_cnt_dis [N_DIS];
__device__ int   g_cnt_drug[N_DRUG];
__device__ int   g_off_dis [N_DIS],  g_cur_dis [N_DIS];
__device__ int   g_off_drug[N_DRUG], g_cur_drug[N_DRUG];
__device__ int   g_eidx_dis [NE];   // d2di edges grouped by dis dst (stores drug src)
__device__ int   g_eidx_drug[NE];   // di2dr edges grouped by drug dst (stores dis src)
__device__ float g_dis_L1_0 [(size_t)N_DIS  * HDIM];   // compact over l_dis_s0
__device__ float g_dis_L1_1 [(size_t)NB     * HDIM];   // compact over l_dis_s1
__device__ float g_drug_L1_0[(size_t)NB     * HDIM];   // compact over l_drug_s0
__device__ float g_drug_L1_1[(size_t)N_DRUG * HDIM];   // compact over l_drug_s1
__device__ float g_drug_L2 [(size_t)NB * HDIM];
__device__ float g_dis_L2  [(size_t)NB * HDIM];
__device__ int g_m_dis_s0[N_DIS],  g_m_dis_s1[N_DIS],  g_m_dis_ag[N_DIS];
__device__ int g_m_drug_s0[N_DRUG],g_m_drug_s1[N_DRUG],g_m_drug_ag[N_DRUG];
__device__ int g_l_dis_s0[N_DIS],  g_l_dis_s1[N_DIS],  g_l_dis_ag[N_DIS];
__device__ int g_l_drug_s0[N_DRUG],g_l_drug_s1[N_DRUG],g_l_drug_ag[N_DRUG];
__device__ int g_s_dis_s0[N_DIS],  g_s_dis_s1[N_DIS],  g_s_dis_ag[N_DIS];
__device__ int g_s_drug_s0[N_DRUG],g_s_drug_s1[N_DRUG],g_s_drug_ag[N_DRUG];
__device__ int g_a1_dis_s0[N_DIS], g_a1_dis_s1[NB], g_a1_drug_s0[NB], g_a1_drug_s1[N_DRUG];
__device__ int g_gd[NB], g_gs[NB];
__device__ int g_ctr[8];
__device__ int g_tsum[2][PSB*PST], g_bsum[2][PSB], g_bsum2[2][PSB];
__device__ float g_A0[HDIM*HDIM], g_A1[HDIM*HDIM], g_c0[HDIM], g_c1[HDIM];
__device__ float g_Md[256*HDIM], g_Ms[256*HDIM], g_btil[256];
__device__ float g_H1[(size_t)NB * 256];
__device__ float g_H2[(size_t)NB * HDIM];

// ---------------- init ----------------
__global__ __launch_bounds__(256) void k_init()
{
    int i = blockIdx.x * blockDim.x + threadIdx.x;
    if (i < N_DIS) {
        g_m_dis_s0[i] = 0; g_m_dis_s1[i] = 0; g_m_dis_ag[i] = 0; g_cnt_dis[i] = 0;
    }
    if (i < N_DRUG) {
        g_m_drug_s0[i] = 0; g_m_drug_s1[i] = 0; g_m_drug_ag[i] = 0; g_cnt_drug[i] = 0;
    }
    if (i < 8) g_ctr[i] = 0;
}

// mark targets; record compact slots at claim time
__global__ __launch_bounds__(256) void k_mark(const int* __restrict__ drug_idx,
                                              const int* __restrict__ disease_idx)
{
    int i = blockIdx.x * blockDim.x + threadIdx.x;
    if (i >= NB) return;
    int d = drug_idx[i];
    if (atomicExch(&g_m_drug_s0[d], 1) == 0) {
        int p = atomicAdd(&g_ctr[C_DRUG_S0], 1); g_l_drug_s0[p] = d; g_s_drug_s0[d] = p;
    }
    if (atomicExch(&g_m_drug_ag[d], 1) == 0) {
        int p = atomicAdd(&g_ctr[C_DRUG_AG], 1); g_l_drug_ag[p] = d; g_s_drug_ag[d] = p;
    }
    int s = disease_idx[i];
    if (atomicExch(&g_m_dis_s1[s], 1) == 0) {
        int p = atomicAdd(&g_ctr[C_DIS_S1], 1); g_l_dis_s1[p] = s; g_s_dis_s1[s] = p;
    }
    if (atomicExch(&g_m_dis_ag[s], 1) == 0) {
        int p = atomicAdd(&g_ctr[C_DIS_AG], 1); g_l_dis_ag[p] = s; g_s_dis_ag[s] = p;
    }
}

// merged edge scan: half A over di2dr (degrees of drugs + dis frontier),
// half B over d2di (degrees of diseases + drug frontier)
__global__ __launch_bounds__(256) void k_scan(const int* __restrict__ srcA, const int* __restrict__ dstA,
                                              const int* __restrict__ srcB, const int* __restrict__ dstB)
{
    int e = blockIdx.x * blockDim.x + threadIdx.x;
    if (e < NE) {
        int d = dstA[e];
        atomicAdd(&g_cnt_drug[d], 1);
        if (g_m_drug_s0[d]) {
            int s = srcA[e];
            if (atomicExch(&g_m_dis_s0[s], 1) == 0) {
                int p = atomicAdd(&g_ctr[C_DIS_S0], 1); g_l_dis_s0[p] = s; g_s_dis_s0[s] = p;
            }
            if (atomicExch(&g_m_dis_ag[s], 1) == 0) {
                int p = atomicAdd(&g_ctr[C_DIS_AG], 1); g_l_dis_ag[p] = s; g_s_dis_ag[s] = p;
            }
        }
    } else if (e < 2 * NE) {
        int e2 = e - NE;
        int d = dstB[e2];
        atomicAdd(&g_cnt_dis[d], 1);
        if (g_m_dis_s1[d]) {
            int s = srcB[e2];
            if (atomicExch(&g_m_drug_s1[s], 1) == 0) {
                int p = atomicAdd(&g_ctr[C_DRUG_S1], 1); g_l_drug_s1[p] = s; g_s_drug_s1[s] = p;
            }
            if (atomicExch(&g_m_drug_ag[s], 1) == 0) {
                int p = atomicAdd(&g_ctr[C_DRUG_AG], 1); g_l_drug_ag[p] = s; g_s_drug_ag[s] = p;
            }
        }
    }
}

// ---------------- 3-phase exclusive prefix scan of degree arrays ----------------
// y==0: dis (N_DIS, R=2)   y==1: drug (N_DRUG, R=4)
__global__ __launch_bounds__(PST) void k_psum1()
{
    int y = blockIdx.y;
    const int* cnt = y ? g_cnt_drug : g_cnt_dis;
    int N = y ? N_DRUG : N_DIS;
    int R = y ? 4 : 2;
    int t = threadIdx.x, b = blockIdx.x;
    int g = b * PST + t;
    int base = g * R, s = 0;
    for (int i = 0; i < R; ++i) { int idx = base + i; if (idx < N) s += cnt[idx]; }
    g_tsum[y][g] = s;
    __shared__ int sh[PST];
    sh[t] = s; __syncthreads();
    for (int o = PST / 2; o; o >>= 1) { if (t < o) sh[t] += sh[t + o]; __syncthreads(); }
    if (!t) g_bsum[y][b] = sh[0];
}

__global__ __launch_bounds__(PSB) void k_psum2()
{
    int y = blockIdx.y;
    int t = threadIdx.x;
    __shared__ int sh[PSB];
    int v = g_bsum[y][t];
    sh[t] = v; __syncthreads();
    for (int o = 1; o < PSB; o <<= 1) {
        int a = (t >= o) ? sh[t - o] : 0;
        __syncthreads();
        sh[t] += a;
        __syncthreads();
    }
    g_bsum2[y][t] = sh[t] - v;   // exclusive
}

__global__ __launch_bounds__(PST) void k_psum3()
{
    int y = blockIdx.y;
    const int* cnt = y ? g_cnt_drug : g_cnt_dis;
    int* off = y ? g_off_drug : g_off_dis;
    int* cur = y ? g_cur_drug : g_cur_dis;
    int N = y ? N_DRUG : N_DIS;
    int R = y ? 4 : 2;
    int t = threadIdx.x, b = blockIdx.x;
    int g = b * PST + t;
    __shared__ int sh[PST];
    int v = g_tsum[y][g];
    sh[t] = v; __syncthreads();
    for (int o = 1; o < PST; o <<= 1) {
        int a = (t >= o) ? sh[t - o] : 0;
        __syncthreads();
        sh[t] += a;
        __syncthreads();
    }
    int run = g_bsum2[y][b] + sh[t] - v;
    int base = g * R;
    for (int i = 0; i < R; ++i) {
        int idx = base + i;
        if (idx < N) { off[idx] = run; cur[idx] = run; run += cnt[idx]; }
    }
}

// scatter edges into CSR slots (1 int atomic per edge)
__global__ __launch_bounds__(256) void k_scatter(const int* __restrict__ srcA, const int* __restrict__ dstA,
                                                 const int* __restrict__ srcB, const int* __restrict__ dstB)
{
    int e = blockIdx.x * blockDim.x + threadIdx.x;
    if (e < NE) {                       // d2di -> group by dis
        int slot = atomicAdd(&g_cur_dis[dstA[e]], 1);
        g_eidx_dis[slot] = srcA[e];
    } else if (e < 2 * NE) {            // di2dr -> group by drug
        int e2 = e - NE;
        int slot = atomicAdd(&g_cur_drug[dstB[e2]], 1);
        g_eidx_drug[slot] = srcB[e2];
    }
}

// warp-per-node gather-mean: out[r] = mean_{s in N(node)} X[map(s)]
__global__ __launch_bounds__(256) void k_gather(const int* __restrict__ list,
                                                const int* __restrict__ cntp,
                                                const int* __restrict__ off,
                                                const int* __restrict__ deg,
                                                const int* __restrict__ eidx,
                                                const int* __restrict__ slotmap,
                                                const float* __restrict__ X,
                                                float* __restrict__ out)
{
    int w = (blockIdx.x * blockDim.x + threadIdx.x) >> 5;
    int lane = threadIdx.x & 31;
    if (w >= *cntp) return;
    int node = list[w];
    int o = off[node];
    int dgr = deg[node];
    float4 acc = make_float4(0.f, 0.f, 0.f, 0.f);
    for (int i = 0; i < dgr; ++i) {
        int s = __ldg(eidx + o + i);
        int row = slotmap ? slotmap[s] : s;
        float4 v = ((const float4*)(X + (size_t)row * HDIM))[lane];
        acc.x += v.x; acc.y += v.y; acc.z += v.z; acc.w += v.w;
    }
    float inv = dgr ? 1.f / (float)dgr : 0.f;
    acc.x *= inv; acc.y *= inv; acc.z *= inv; acc.w *= inv;
    ((float4*)(out + (size_t)w * HDIM))[lane] = acc;
}

// compose per-row gather indices (6 segments via blockIdx.y)
__global__ __launch_bounds__(256) void k_compose(const int* __restrict__ drug_idx,
                                                 const int* __restrict__ disease_idx)
{
    int y = blockIdx.y;
    int i = blockIdx.x * blockDim.x + threadIdx.x;
    switch (y) {
    case 0: if (i < g_ctr[C_DIS_S0])  g_a1_dis_s0[i]  = g_s_dis_ag[g_l_dis_s0[i]];   break;
    case 1: if (i < g_ctr[C_DIS_S1])  g_a1_dis_s1[i]  = g_s_dis_ag[g_l_dis_s1[i]];   break;
    case 2: if (i < g_ctr[C_DRUG_S0]) g_a1_drug_s0[i] = g_s_drug_ag[g_l_drug_s0[i]]; break;
    case 3: if (i < g_ctr[C_DRUG_S1]) g_a1_drug_s1[i] = g_s_drug_ag[g_l_drug_s1[i]]; break;
    case 4: if (i < NB)               g_gd[i]         = g_s_drug_s0[drug_idx[i]];    break;
    case 5: if (i < NB)               g_gs[i]         = g_s_dis_s1[disease_idx[i]];  break;
    }
}

// ---------------- tiled SGEMM with packed f32x2 FMA ----------------
// out[r, n0+n] = act( sum_{k<K1} X1[a1,k]*Wa[n0+n,k] + sum_{k>=K1} X2[a2,k-K1]*Wb[..] + bias )
// a1 = g1 ? g1[r] : r ; a2 = g2 ? g2[r] : r ; out row = r (compact)
#define TMR 64
#define KCH 32

#define FMA2(d, a, b) asm("fma.rn.f32x2 %0, %1, %2, %0;" : "+l"(d) : "l"(a), "l"(b))

__global__ __launch_bounds__(256) void k_gemm(
    const int* __restrict__ rowcnt, int nfixed,
    const float* __restrict__ X1, const int* __restrict__ g1,
    const float* __restrict__ X2, const int* __restrict__ g2,
    int K1, int K,
    const float* __restrict__ Wa, const float* __restrict__ Wb,
    const float* __restrict__ bias,
    float* __restrict__ out, int Nout, int relu)
{
    __shared__ float As[TMR][KCH + 1];
    __shared__ float Ws[KCH][128];
    __shared__ int   s_a1[TMR], s_a2[TMR], s_ok[TMR];

    int nr = rowcnt ? *rowcnt : nfixed;
    int row0 = blockIdx.x * TMR;
    if (row0 >= nr) return;
    int t = threadIdx.x;
    int n0 = blockIdx.y * 128;

    if (t < TMR) {
        int r = row0 + t;
        int ok = r < nr;
        s_a1[t] = ok ? (g1 ? g1[r] : r) : 0;
        s_a2[t] = ok ? (g2 ? g2[r] : r) : 0;
        s_ok[t] = ok;
    }
    __syncthreads();

    unsigned long long acc2[4][4];
#pragma unroll
    for (int i = 0; i < 4; ++i)
#pragma unroll
        for (int j = 0; j < 4; ++j) acc2[i][j] = 0ULL;

    int tx = t & 15;
    int ty = t >> 4;
    int K2 = K - K1;
    int nch = K / KCH;

    for (int c = 0; c < nch; ++c) {
        int kb = c * KCH;
        {   // A tile
            int i  = t >> 2;
            int k0 = (t & 3) * 8;
            float4 v0 = make_float4(0.f, 0.f, 0.f, 0.f), v1 = v0;
            if (s_ok[i]) {
                int k = kb + k0;
                if (k < K1) {
                    const float4* p = (const float4*)(X1 + (size_t)s_a1[i] * K1 + k);
                    v0 = p[0]; v1 = p[1];
                } else {
                    const float4* p = (const float4*)(X2 + (size_t)s_a2[i] * K2 + (k - K1));
                    v0 = p[0]; v1 = p[1];
                }
            }
            As[i][k0+0] = v0.x; As[i][k0+1] = v0.y; As[i][k0+2] = v0.z; As[i][k0+3] = v0.w;
            As[i][k0+4] = v1.x; As[i][k0+5] = v1.y; As[i][k0+6] = v1.z; As[i][k0+7] = v1.w;
        }
        {   // W tile
            int n  = t >> 1;
            int k0 = (t & 1) * 16;
            int gk = kb + k0;
            const float* wp = (gk < K1) ? (Wa + (size_t)(n0 + n) * K1 + gk)
                                        : (Wb + (size_t)(n0 + n) * K2 + (gk - K1));
#pragma unroll
            for (int j = 0; j < 16; j += 4) {
                float4 w = *(const float4*)(wp + j);
                Ws[k0+j+0][n] = w.x; Ws[k0+j+1][n] = w.y;
                Ws[k0+j+2][n] = w.z; Ws[k0+j+3][n] = w.w;
            }
        }
        __syncthreads();
#pragma unroll
        for (int kk = 0; kk < KCH; ++kk) {
            ulonglong2 wA = ((const ulonglong2*)&Ws[kk][tx * 8])[0];
            ulonglong2 wB = ((const ulonglong2*)&Ws[kk][tx * 8])[1];
#pragma unroll
            for (int i = 0; i < 4; ++i) {
                unsigned au = __float_as_uint(As[ty * 4 + i][kk]);
                unsigned long long ap;
                asm("mov.b64 %0, {%1, %1};" : "=l"(ap) : "r"(au));
                FMA2(acc2[i][0], ap, wA.x);
                FMA2(acc2[i][1], ap, wA.y);
                FMA2(acc2[i][2], ap, wB.x);
                FMA2(acc2[i][3], ap, wB.y);
            }
        }
        __syncthreads();
    }

    float b[8];
#pragma unroll
    for (int j = 0; j < 8; ++j) b[j] = bias[n0 + tx * 8 + j];
#pragma unroll
    for (int i = 0; i < 4; ++i) {
        int ri = ty * 4 + i;
        if (!s_ok[ri]) continue;
        float ov[8];
#pragma unroll
        for (int p2 = 0; p2 < 4; ++p2) {
            unsigned lo, hi;
            asm("mov.b64 {%0, %1}, %2;" : "=r"(lo), "=r"(hi) : "l"(acc2[i][p2]));
            ov[2*p2]   = __uint_as_float(lo) + b[2*p2];
            ov[2*p2+1] = __uint_as_float(hi) + b[2*p2+1];
        }
        if (relu) {
#pragma unroll
            for (int j = 0; j < 8; ++j) ov[j] = fmaxf(ov[j], 0.f);
        }
        float* op = out + (size_t)(row0 + ri) * Nout + n0 + tx * 8;
        ((float4*)op)[0] = make_float4(ov[0], ov[1], ov[2], ov[3]);
        ((float4*)op)[1] = make_float4(ov[4], ov[5], ov[6], ov[7]);
    }
}

// fold attention (len-1 kv => softmax == 1): A_m = Wout_m @ Wv_m, c_m = Wout_m@bv_m + bout_m
__global__ __launch_bounds__(128) void k_fold1(const float* __restrict__ Win,
                                               const float* __restrict__ bin,
                                               const float* __restrict__ Wout,
                                               const float* __restrict__ bout)
{
    int m = blockIdx.y;
    int tt = blockIdx.x;
    int j = threadIdx.x;
    const float* Wv = Win + (size_t)m * 384 * 128 + 256 * 128;
    const float* Wo = Wout + (size_t)m * 128 * 128;
    const float* bv = bin + m * 384 + 256;
    const float* bo = bout + m * 128;
    const float* worow = Wo + (size_t)tt * 128;
    float s = 0.f;
    for (int u = 0; u < 128; ++u) s += worow[u] * Wv[(size_t)u * 128 + j];
    (m == 0 ? g_A0 : g_A1)[tt * 128 + j] = s;
    __shared__ float red[128];
    red[j] = worow[j] * bv[j];
    __syncthreads();
    for (int o = 64; o > 0; o >>= 1) { if (j < o) red[j] += red[j + o]; __syncthreads(); }
    if (j == 0) (m == 0 ? g_c0 : g_c1)[tt] = red[0] + bo[tt];
}

// fold attention affine maps into mlp_W1: h1 = relu(Md*de + Ms*se + btil)
__global__ __launch_bounds__(128) void k_fold2(const float* __restrict__ W1,
                                               const float* __restrict__ b1)
{
    int o = blockIdx.x, j = threadIdx.x;
    const float* wrow = W1 + (size_t)o * 512;
    float md = wrow[j];
    float ms = wrow[128 + j];
    for (int tt = 0; tt < 128; ++tt) {
        ms += wrow[256 + tt] * g_A0[tt * 128 + j];
        md += wrow[384 + tt] * g_A1[tt * 128 + j];
    }
    g_Md[o * 128 + j] = md;
    g_Ms[o * 128 + j] = ms;
    __shared__ float red[128];
    red[j] = wrow[256 + j] * g_c0[j] + wrow[384 + j] * g_c1[j];
    __syncthreads();
    for (int t2 = 64; t2 > 0; t2 >>= 1) { if (j < t2) red[j] += red[j + t2]; __syncthreads(); }
    if (j == 0) g_btil[o] = red[0] + b1[o];
}

__global__ __launch_bounds__(256) void k_dot(const float* __restrict__ H2,
                                             const float* __restrict__ W3,
                                             const float* __restrict__ b3,
                                             float* __restrict__ out)
{
    int w = (blockIdx.x * blockDim.x + threadIdx.x) >> 5;
    int lane = threadIdx.x & 31;
    if (w >= NB) return;
    float4 h = ((const float4*)(H2 + (size_t)w * 128))[lane];
    float4 c = ((const float4*)W3)[lane];
    float s = h.x * c.x + h.y * c.y + h.z * c.z + h.w * c.w;
    for (int o = 16; o; o >>= 1) s += __shfl_xor_sync(0xffffffffu, s, o);
    if (lane == 0) out[w] = s + b3[0];
}

// ---------------- host ----------------
static inline int ceildiv(int a, int b) { return (a + b - 1) / b; }

extern "C" void kernel_launch(void* const* d_in, const int* in_sizes, int n_in,
                              void* d_out, int out_size)
{
    int fi, ii;
    if (in_sizes[0] == NE) { ii = 0; fi = 6; } else { fi = 0; ii = 15; }
    const float* emb_drug  = (const float*)d_in[fi + 0];
    const float* emb_dis   = (const float*)d_in[fi + 1];
    const float* conv_Wl   = (const float*)d_in[fi + 2];
    const float* conv_bl   = (const float*)d_in[fi + 3];
    const float* conv_Wr   = (const float*)d_in[fi + 4];
    const float* attn_Win  = (const float*)d_in[fi + 5];
    const float* attn_bin  = (const float*)d_in[fi + 6];
    const float* attn_Wout = (const float*)d_in[fi + 7];
    const float* attn_bout = (const float*)d_in[fi + 8];
    const float* mlp_W1    = (const float*)d_in[fi + 9];
    const float* mlp_b1    = (const float*)d_in[fi + 10];
    const float* mlp_W2    = (const float*)d_in[fi + 11];
    const float* mlp_b2    = (const float*)d_in[fi + 12];
    const float* mlp_W3    = (const float*)d_in[fi + 13];
    const float* mlp_b3    = (const float*)d_in[fi + 14];
    const int* src_d2di    = (const int*)d_in[ii + 0];
    const int* dst_d2di    = (const int*)d_in[ii + 1];
    const int* src_di2dr   = (const int*)d_in[ii + 2];
    const int* dst_di2dr   = (const int*)d_in[ii + 3];
    const int* drug_idx    = (const int*)d_in[ii + 4];
    const int* disease_idx = (const int*)d_in[ii + 5];
    float* out = (float*)d_out;

    void* p;
    cudaGetSymbolAddress(&p, g_aggc_dis);   float* aggc_dis   = (float*)p;
    cudaGetSymbolAddress(&p, g_aggc_drug);  float* aggc_drug  = (float*)p;
    cudaGetSymbolAddress(&p, g_cnt_dis);    int*   cnt_dis    = (int*)p;
    cudaGetSymbolAddress(&p, g_cnt_drug);   int*   cnt_drug   = (int*)p;
    cudaGetSymbolAddress(&p, g_off_dis);    int*   off_dis    = (int*)p;
    cudaGetSymbolAddress(&p, g_off_drug);   int*   off_drug   = (int*)p;
    cudaGetSymbolAddress(&p, g_eidx_dis);   int*   eidx_dis   = (int*)p;
    cudaGetSymbolAddress(&p, g_eidx_drug);  int*   eidx_drug  = (int*)p;
    cudaGetSymbolAddress(&p, g_dis_L1_0);   float* dis_L1_0   = (float*)p;
    cudaGetSymbolAddress(&p, g_dis_L1_1);   float* dis_L1_1   = (float*)p;
    cudaGetSymbolAddress(&p, g_drug_L1_0);  float* drug_L1_0  = (float*)p;
    cudaGetSymbolAddress(&p, g_drug_L1_1);  float* drug_L1_1  = (float*)p;
    cudaGetSymbolAddress(&p, g_drug_L2);    float* drug_L2    = (float*)p;
    cudaGetSymbolAddress(&p, g_dis_L2);     float* dis_L2     = (float*)p;
    cudaGetSymbolAddress(&p, g_l_dis_s0);   int* l_dis_s0     = (int*)p;
    cudaGetSymbolAddress(&p, g_l_dis_s1);   int* l_dis_s1     = (int*)p;
    cudaGetSymbolAddress(&p, g_l_dis_ag);   int* l_dis_ag     = (int*)p;
    cudaGetSymbolAddress(&p, g_l_drug_s0);  int* l_drug_s0    = (int*)p;
    cudaGetSymbolAddress(&p, g_l_drug_s1);  int* l_drug_s1    = (int*)p;
    cudaGetSymbolAddress(&p, g_l_drug_ag);  int* l_drug_ag    = (int*)p;
    cudaGetSymbolAddress(&p, g_s_dis_s0);   int* s_dis_s0     = (int*)p;
    cudaGetSymbolAddress(&p, g_s_drug_s1);  int* s_drug_s1    = (int*)p;
    cudaGetSymbolAddress(&p, g_a1_dis_s0);  int* a1_dis_s0    = (int*)p;
    cudaGetSymbolAddress(&p, g_a1_dis_s1);  int* a1_dis_s1    = (int*)p;
    cudaGetSymbolAddress(&p, g_a1_drug_s0); int* a1_drug_s0   = (int*)p;
    cudaGetSymbolAddress(&p, g_a1_drug_s1); int* a1_drug_s1   = (int*)p;
    cudaGetSymbolAddress(&p, g_gd);         int* gd           = (int*)p;
    cudaGetSymbolAddress(&p, g_gs);         int* gs           = (int*)p;
    cudaGetSymbolAddress(&p, g_ctr);        int* ctr          = (int*)p;
    cudaGetSymbolAddress(&p, g_Md);         float* Md         = (float*)p;
    cudaGetSymbolAddress(&p, g_Ms);         float* Ms         = (float*)p;
    cudaGetSymbolAddress(&p, g_btil);       float* btil       = (float*)p;
    cudaGetSymbolAddress(&p, g_H1);         float* H1         = (float*)p;
    cudaGetSymbolAddress(&p, g_H2);         float* H2         = (float*)p;

    auto woff = [](int s, int l, int et) { return (size_t)((s * 2 + l) * 2 + et) * 128 * 128; };
    auto boff = [](int s, int l, int et) { return (size_t)((s * 2 + l) * 2 + et) * 128; };

    // 1. init + mark + merged scan
    k_init<<<ceildiv(N_DRUG, 256), 256>>>();
    k_mark<<<ceildiv(NB, 256), 256>>>(drug_idx, disease_idx);
    k_scan<<<ceildiv(2 * NE, 256), 256>>>(src_di2dr, dst_di2dr, src_d2di, dst_d2di);
    // 2. CSR build: prefix scan of degrees + scatter
    k_psum1<<<dim3(PSB, 2), PST>>>();
    k_psum2<<<dim3(1, 2), PSB>>>();
    k_psum3<<<dim3(PSB, 2), PST>>>();
    k_scatter<<<ceildiv(2 * NE, 256), 256>>>(src_d2di, dst_d2di, src_di2dr, dst_di2dr);
    // 3. L1 gather-mean (compact, ag-list order)
    k_gather<<<ceildiv(N_DIS * 32, 256), 256>>>(l_dis_ag, ctr + C_DIS_AG, off_dis, cnt_dis,
                                                eidx_dis, nullptr, emb_drug, aggc_dis);
    k_gather<<<ceildiv(N_DRUG * 32, 256), 256>>>(l_drug_ag, ctr + C_DRUG_AG, off_drug, cnt_drug,
                                                 eidx_drug, nullptr, emb_dis, aggc_drug);
    // 4. per-row gather index composition
    k_compose<<<dim3(ceildiv(N_DRUG, 256), 6), 256>>>(drug_idx, disease_idx);
    // 5. L1 GEMMs
    k_gemm<<<ceildiv(N_DIS, TMR), 256>>>(ctr + C_DIS_S0, 0, aggc_dis, a1_dis_s0, emb_dis, l_dis_s0,
                        128, 256, conv_Wl + woff(0,0,0), conv_Wr + woff(0,0,0), conv_bl + boff(0,0,0),
                        dis_L1_0, 128, 1);
    k_gemm<<<ceildiv(NB, TMR), 256>>>(ctr + C_DIS_S1, 0, aggc_dis, a1_dis_s1, emb_dis, l_dis_s1,
                        128, 256, conv_Wl + woff(1,0,0), conv_Wr + woff(1,0,0), conv_bl + boff(1,0,0),
                        dis_L1_1, 128, 1);
    k_gemm<<<ceildiv(NB, TMR), 256>>>(ctr + C_DRUG_S0, 0, aggc_drug, a1_drug_s0, emb_drug, l_drug_s0,
                        128, 256, conv_Wl + woff(0,0,1), conv_Wr + woff(0,0,1), conv_bl + boff(0,0,1),
                        drug_L1_0, 128, 1);
    k_gemm<<<ceildiv(N_DRUG, TMR), 256>>>(ctr + C_DRUG_S1, 0, aggc_drug, a1_drug_s1, emb_drug, l_drug_s1,
                        128, 256, conv_Wl + woff(1,0,1), conv_Wr + woff(1,0,1), conv_bl + boff(1,0,1),
                        drug_L1_1, 128, 1);
    // 6. L2 gather-mean (targets only; reuse aggc buffers, L1 GEMMs already consumed them)
    k_gather<<<ceildiv(NB * 32, 256), 256>>>(l_drug_s0, ctr + C_DRUG_S0, off_drug, cnt_drug,
                                             eidx_drug, s_dis_s0, dis_L1_0, aggc_drug);
    k_gather<<<ceildiv(NB * 32, 256), 256>>>(l_dis_s1, ctr + C_DIS_S1, off_dis, cnt_dis,
                                             eidx_dis, s_drug_s1, drug_L1_1, aggc_dis);
    // 7. L2 GEMMs (compact rows, same list order as their inputs)
    k_gemm<<<ceildiv(NB, TMR), 256>>>(ctr + C_DRUG_S0, 0, aggc_drug, nullptr, drug_L1_0, nullptr,
                        128, 256, conv_Wl + woff(0,1,1), conv_Wr + woff(0,1,1), conv_bl + boff(0,1,1),
                        drug_L2, 128, 1);
    k_gemm<<<ceildiv(NB, TMR), 256>>>(ctr + C_DIS_S1, 0, aggc_dis, nullptr, dis_L1_1, nullptr,
                        128, 256, conv_Wl + woff(1,1,0), conv_Wr + woff(1,1,0), conv_bl + boff(1,1,0),
                        dis_L2, 128, 1);
    // 8. fold degenerate MHA into MLP layer 1
    k_fold1<<<dim3(128, 2), 128>>>(attn_Win, attn_bin, attn_Wout, attn_bout);
    k_fold2<<<256, 128>>>(mlp_W1, mlp_b1);
    // 9. pair head
    k_gemm<<<dim3(ceildiv(NB, TMR), 2), 256>>>(nullptr, NB, drug_L2, gd, dis_L2, gs,
                        128, 256, Md, Ms, btil, H1, 256, 1);
    k_gemm<<<dim3(ceildiv(NB, TMR), 1), 256>>>(nullptr, NB, H1, nullptr, H1, nullptr,
                        256, 256, mlp_W2, mlp_W2, mlp_b2, H2, 128, 1);
    k_dot<<<ceildiv(NB * 32, 256), 256>>>(H2, mlp_W3, mlp_b3, out);
}

// round 9
// speedup vs baseline: 1.3965x; 1.0132x over previous
#include <cuda_runtime.h>
#include <cuda_bf16.h>
#include <cstdint>

#define N_DRUG 200000
#define N_DIS  100000
#define HDIM   128
#define NE     600000
#define NB     8192

#define C_DIS_S0  0
#define C_DIS_S1  1
#define C_DIS_AG  2
#define C_DRUG_S0 3
#define C_DRUG_S1 4
#define C_DRUG_AG 5

// ---------------- device scratch ----------------
__device__ float g_aggc_dis [(size_t)N_DIS  * HDIM];   // L1 agg compact (ag-list order); reused for L2 dis agg
__device__ float g_aggc_drug[(size_t)N_DRUG * HDIM];   // same for drugs; reused for L2 drug agg
__device__ int   g_head_dis [N_DIS];    // d2di edges chained by dis dst
__device__ int   g_head_drug[N_DRUG];   // di2dr edges chained by drug dst
__device__ int   g_next_dis [NE];
__device__ int   g_next_drug[NE];
__device__ float g_dis_L1_0 [(size_t)N_DIS  * HDIM];   // compact over l_dis_s0
__device__ float g_dis_L1_1 [(size_t)NB     * HDIM];   // compact over l_dis_s1
__device__ float g_drug_L1_0[(size_t)NB     * HDIM];   // compact over l_drug_s0
__device__ float g_drug_L1_1[(size_t)N_DRUG * HDIM];   // compact over l_drug_s1
__device__ float g_drug_L2 [(size_t)NB * HDIM];
__device__ float g_dis_L2  [(size_t)NB * HDIM];
__device__ int g_m_dis_s0[N_DIS],  g_m_dis_s1[N_DIS],  g_m_dis_ag[N_DIS];
__device__ int g_m_drug_s0[N_DRUG],g_m_drug_s1[N_DRUG],g_m_drug_ag[N_DRUG];
__device__ int g_l_dis_s0[N_DIS],  g_l_dis_s1[N_DIS],  g_l_dis_ag[N_DIS];
__device__ int g_l_drug_s0[N_DRUG],g_l_drug_s1[N_DRUG],g_l_drug_ag[N_DRUG];
__device__ int g_s_dis_s0[N_DIS],  g_s_dis_s1[N_DIS],  g_s_dis_ag[N_DIS];
__device__ int g_s_drug_s0[N_DRUG],g_s_drug_s1[N_DRUG],g_s_drug_ag[N_DRUG];
__device__ int g_a1_dis_s0[N_DIS], g_a1_dis_s1[NB], g_a1_drug_s0[NB], g_a1_drug_s1[N_DRUG];
__device__ int g_gd[NB], g_gs[NB];
__device__ int g_ctr[8];
__device__ float g_A0[HDIM*HDIM], g_A1[HDIM*HDIM], g_c0[HDIM], g_c1[HDIM];
__device__ float g_Md[256*HDIM], g_Ms[256*HDIM], g_btil[256];
__device__ float g_H1[(size_t)NB * 256];
__device__ float g_H2[(size_t)NB * HDIM];

// ---------------- init: masks + chain heads + counters ----------------
__global__ __launch_bounds__(256) void k_init()
{
    int i = blockIdx.x * blockDim.x + threadIdx.x;
    if (i < N_DIS) {
        g_m_dis_s0[i] = 0; g_m_dis_s1[i] = 0; g_m_dis_ag[i] = 0; g_head_dis[i] = -1;
    }
    if (i < N_DRUG) {
        g_m_drug_s0[i] = 0; g_m_drug_s1[i] = 0; g_m_drug_ag[i] = 0; g_head_drug[i] = -1;
    }
    if (i < 8) g_ctr[i] = 0;
}

// mark targets; record compact slots at claim time
__global__ __launch_bounds__(256) void k_mark(const int* __restrict__ drug_idx,
                                              const int* __restrict__ disease_idx)
{
    int i = blockIdx.x * blockDim.x + threadIdx.x;
    if (i >= NB) return;
    int d = drug_idx[i];
    if (atomicExch(&g_m_drug_s0[d], 1) == 0) {
        int p = atomicAdd(&g_ctr[C_DRUG_S0], 1); g_l_drug_s0[p] = d; g_s_drug_s0[d] = p;
    }
    if (atomicExch(&g_m_drug_ag[d], 1) == 0) {
        int p = atomicAdd(&g_ctr[C_DRUG_AG], 1); g_l_drug_ag[p] = d; g_s_drug_ag[d] = p;
    }
    int s = disease_idx[i];
    if (atomicExch(&g_m_dis_s1[s], 1) == 0) {
        int p = atomicAdd(&g_ctr[C_DIS_S1], 1); g_l_dis_s1[p] = s; g_s_dis_s1[s] = p;
    }
    if (atomicExch(&g_m_dis_ag[s], 1) == 0) {
        int p = atomicAdd(&g_ctr[C_DIS_AG], 1); g_l_dis_ag[p] = s; g_s_dis_ag[s] = p;
    }
}

// one-pass linked-list CSR: next[e] = atomicExch(head[dst], e)
__global__ __launch_bounds__(256) void k_link(const int* __restrict__ dst_d2di,
                                              const int* __restrict__ dst_di2dr)
{
    int e = blockIdx.x * blockDim.x + threadIdx.x;
    if (e < NE) {
        int d = dst_d2di[e];                 // disease dst
        g_next_dis[e] = atomicExch(&g_head_dis[d], e);
    } else if (e < 2 * NE) {
        int e2 = e - NE;
        int d = dst_di2dr[e2];               // drug dst
        g_next_drug[e2] = atomicExch(&g_head_drug[d], e2);
    }
}

// frontier discovery by walking chains of target nodes only
__global__ __launch_bounds__(256) void k_frontier(const int* __restrict__ src_di2dr,
                                                  const int* __restrict__ src_d2di)
{
    int y = blockIdx.y;
    int i = blockIdx.x * blockDim.x + threadIdx.x;
    if (y == 0) {
        if (i >= g_ctr[C_DRUG_S0]) return;
        int d = g_l_drug_s0[i];
        for (int e = g_head_drug[d]; e >= 0; e = __ldg(g_next_drug + e)) {
            int s = __ldg(src_di2dr + e);    // disease neighbor
            if (atomicExch(&g_m_dis_s0[s], 1) == 0) {
                int p = atomicAdd(&g_ctr[C_DIS_S0], 1); g_l_dis_s0[p] = s; g_s_dis_s0[s] = p;
            }
            if (atomicExch(&g_m_dis_ag[s], 1) == 0) {
                int p = atomicAdd(&g_ctr[C_DIS_AG], 1); g_l_dis_ag[p] = s; g_s_dis_ag[s] = p;
            }
        }
    } else {
        if (i >= g_ctr[C_DIS_S1]) return;
        int ds = g_l_dis_s1[i];
        for (int e = g_head_dis[ds]; e >= 0; e = __ldg(g_next_dis + e)) {
            int s = __ldg(src_d2di + e);     // drug neighbor
            if (atomicExch(&g_m_drug_s1[s], 1) == 0) {
                int p = atomicAdd(&g_ctr[C_DRUG_S1], 1); g_l_drug_s1[p] = s; g_s_drug_s1[s] = p;
            }
            if (atomicExch(&g_m_drug_ag[s], 1) == 0) {
                int p = atomicAdd(&g_ctr[C_DRUG_AG], 1); g_l_drug_ag[p] = s; g_s_drug_ag[s] = p;
            }
        }
    }
}

// warp-per-node chain-walk gather-mean: out[r] = mean_{e in chain(node)} X[map(src[e])]
__global__ __launch_bounds__(256) void k_gather(const int* __restrict__ list,
                                                const int* __restrict__ cntp,
                                                const int* __restrict__ head,
                                                const int* __restrict__ next,
                                                const int* __restrict__ srcArr,
                                                const int* __restrict__ slotmap,
                                                const float* __restrict__ X,
                                                float* __restrict__ out)
{
    int w = (blockIdx.x * blockDim.x + threadIdx.x) >> 5;
    int lane = threadIdx.x & 31;
    if (w >= *cntp) return;
    int node = list[w];
    float4 acc = make_float4(0.f, 0.f, 0.f, 0.f);
    int n = 0;
    int e = head[node];
    while (e >= 0) {
        int nx = __ldg(next + e);
        int s = __ldg(srcArr + e);
        int row = slotmap ? slotmap[s] : s;
        float4 v = ((const float4*)(X + (size_t)row * HDIM))[lane];
        acc.x += v.x; acc.y += v.y; acc.z += v.z; acc.w += v.w;
        ++n;
        e = nx;
    }
    float inv = n ? 1.f / (float)n : 0.f;
    acc.x *= inv; acc.y *= inv; acc.z *= inv; acc.w *= inv;
    ((float4*)(out + (size_t)w * HDIM))[lane] = acc;
}

// compose per-row gather indices (6 segments via blockIdx.y)
__global__ __launch_bounds__(256) void k_compose(const int* __restrict__ drug_idx,
                                                 const int* __restrict__ disease_idx)
{
    int y = blockIdx.y;
    int i = blockIdx.x * blockDim.x + threadIdx.x;
    switch (y) {
    case 0: if (i < g_ctr[C_DIS_S0])  g_a1_dis_s0[i]  = g_s_dis_ag[g_l_dis_s0[i]];   break;
    case 1: if (i < g_ctr[C_DIS_S1])  g_a1_dis_s1[i]  = g_s_dis_ag[g_l_dis_s1[i]];   break;
    case 2: if (i < g_ctr[C_DRUG_S0]) g_a1_drug_s0[i] = g_s_drug_ag[g_l_drug_s0[i]]; break;
    case 3: if (i < g_ctr[C_DRUG_S1]) g_a1_drug_s1[i] = g_s_drug_ag[g_l_drug_s1[i]]; break;
    case 4: if (i < NB)               g_gd[i]         = g_s_drug_s0[drug_idx[i]];    break;
    case 5: if (i < NB)               g_gs[i]         = g_s_dis_s1[disease_idx[i]];  break;
    }
}

// ---------------- tiled SGEMM with packed f32x2 FMA ----------------
#define TMR 64
#define KCH 32

#define FMA2(d, a, b) asm("fma.rn.f32x2 %0, %1, %2, %0;" : "+l"(d) : "l"(a), "l"(b))

__global__ __launch_bounds__(256) void k_gemm(
    const int* __restrict__ rowcnt, int nfixed,
    const float* __restrict__ X1, const int* __restrict__ g1,
    const float* __restrict__ X2, const int* __restrict__ g2,
    int K1, int K,
    const float* __restrict__ Wa, const float* __restrict__ Wb,
    const float* __restrict__ bias,
    float* __restrict__ out, int Nout, int relu)
{
    __shared__ float As[TMR][KCH + 1];
    __shared__ float Ws[KCH][128];
    __shared__ int   s_a1[TMR], s_a2[TMR], s_ok[TMR];

    int nr = rowcnt ? *rowcnt : nfixed;
    int row0 = blockIdx.x * TMR;
    if (row0 >= nr) return;
    int t = threadIdx.x;
    int n0 = blockIdx.y * 128;

    if (t < TMR) {
        int r = row0 + t;
        int ok = r < nr;
        s_a1[t] = ok ? (g1 ? g1[r] : r) : 0;
        s_a2[t] = ok ? (g2 ? g2[r] : r) : 0;
        s_ok[t] = ok;
    }
    __syncthreads();

    unsigned long long acc2[4][4];
#pragma unroll
    for (int i = 0; i < 4; ++i)
#pragma unroll
        for (int j = 0; j < 4; ++j) acc2[i][j] = 0ULL;

    int tx = t & 15;
    int ty = t >> 4;
    int K2 = K - K1;
    int nch = K / KCH;

    for (int c = 0; c < nch; ++c) {
        int kb = c * KCH;
        {   // A tile
            int i  = t >> 2;
            int k0 = (t & 3) * 8;
            float4 v0 = make_float4(0.f, 0.f, 0.f, 0.f), v1 = v0;
            if (s_ok[i]) {
                int k = kb + k0;
                if (k < K1) {
                    const float4* p = (const float4*)(X1 + (size_t)s_a1[i] * K1 + k);
                    v0 = p[0]; v1 = p[1];
                } else {
                    const float4* p = (const float4*)(X2 + (size_t)s_a2[i] * K2 + (k - K1));
                    v0 = p[0]; v1 = p[1];
                }
            }
            As[i][k0+0] = v0.x; As[i][k0+1] = v0.y; As[i][k0+2] = v0.z; As[i][k0+3] = v0.w;
            As[i][k0+4] = v1.x; As[i][k0+5] = v1.y; As[i][k0+6] = v1.z; As[i][k0+7] = v1.w;
        }
        {   // W tile
            int n  = t >> 1;
            int k0 = (t & 1) * 16;
            int gk = kb + k0;
            const float* wp = (gk < K1) ? (Wa + (size_t)(n0 + n) * K1 + gk)
                                        : (Wb + (size_t)(n0 + n) * K2 + (gk - K1));
#pragma unroll
            for (int j = 0; j < 16; j += 4) {
                float4 w = *(const float4*)(wp + j);
                Ws[k0+j+0][n] = w.x; Ws[k0+j+1][n] = w.y;
                Ws[k0+j+2][n] = w.z; Ws[k0+j+3][n] = w.w;
            }
        }
        __syncthreads();
#pragma unroll
        for (int kk = 0; kk < KCH; ++kk) {
            ulonglong2 wA = ((const ulonglong2*)&Ws[kk][tx * 8])[0];
            ulonglong2 wB = ((const ulonglong2*)&Ws[kk][tx * 8])[1];
#pragma unroll
            for (int i = 0; i < 4; ++i) {
                unsigned au = __float_as_uint(As[ty * 4 + i][kk]);
                unsigned long long ap;
                asm("mov.b64 %0, {%1, %1};" : "=l"(ap) : "r"(au));
                FMA2(acc2[i][0], ap, wA.x);
                FMA2(acc2[i][1], ap, wA.y);
                FMA2(acc2[i][2], ap, wB.x);
                FMA2(acc2[i][3], ap, wB.y);
            }
        }
        __syncthreads();
    }

    float b[8];
#pragma unroll
    for (int j = 0; j < 8; ++j) b[j] = bias[n0 + tx * 8 + j];
#pragma unroll
    for (int i = 0; i < 4; ++i) {
        int ri = ty * 4 + i;
        if (!s_ok[ri]) continue;
        float ov[8];
#pragma unroll
        for (int p2 = 0; p2 < 4; ++p2) {
            unsigned lo, hi;
            asm("mov.b64 {%0, %1}, %2;" : "=r"(lo), "=r"(hi) : "l"(acc2[i][p2]));
            ov[2*p2]   = __uint_as_float(lo) + b[2*p2];
            ov[2*p2+1] = __uint_as_float(hi) + b[2*p2+1];
        }
        if (relu) {
#pragma unroll
            for (int j = 0; j < 8; ++j) ov[j] = fmaxf(ov[j], 0.f);
        }
        float* op = out + (size_t)(row0 + ri) * Nout + n0 + tx * 8;
        ((float4*)op)[0] = make_float4(ov[0], ov[1], ov[2], ov[3]);
        ((float4*)op)[1] = make_float4(ov[4], ov[5], ov[6], ov[7]);
    }
}

// fold attention (len-1 kv => softmax == 1): A_m = Wout_m @ Wv_m, c_m = Wout_m@bv_m + bout_m
__global__ __launch_bounds__(128) void k_fold1(const float* __restrict__ Win,
                                               const float* __restrict__ bin,
                                               const float* __restrict__ Wout,
                                               const float* __restrict__ bout)
{
    int m = blockIdx.y;
    int tt = blockIdx.x;
    int j = threadIdx.x;
    const float* Wv = Win + (size_t)m * 384 * 128 + 256 * 128;
    const float* Wo = Wout + (size_t)m * 128 * 128;
    const float* bv = bin + m * 384 + 256;
    const float* bo = bout + m * 128;
    const float* worow = Wo + (size_t)tt * 128;
    float s = 0.f;
    for (int u = 0; u < 128; ++u) s += worow[u] * Wv[(size_t)u * 128 + j];
    (m == 0 ? g_A0 : g_A1)[tt * 128 + j] = s;
    __shared__ float red[128];
    red[j] = worow[j] * bv[j];
    __syncthreads();
    for (int o = 64; o > 0; o >>= 1) { if (j < o) red[j] += red[j + o]; __syncthreads(); }
    if (j == 0) (m == 0 ? g_c0 : g_c1)[tt] = red[0] + bo[tt];
}

// fold attention affine maps into mlp_W1: h1 = relu(Md*de + Ms*se + btil)
__global__ __launch_bounds__(128) void k_fold2(const float* __restrict__ W1,
                                               const float* __restrict__ b1)
{
    int o = blockIdx.x, j = threadIdx.x;
    const float* wrow = W1 + (size_t)o * 512;
    float md = wrow[j];
    float ms = wrow[128 + j];
    for (int tt = 0; tt < 128; ++tt) {
        ms += wrow[256 + tt] * g_A0[tt * 128 + j];
        md += wrow[384 + tt] * g_A1[tt * 128 + j];
    }
    g_Md[o * 128 + j] = md;
    g_Ms[o * 128 + j] = ms;
    __shared__ float red[128];
    red[j] = wrow[256 + j] * g_c0[j] + wrow[384 + j] * g_c1[j];
    __syncthreads();
    for (int t2 = 64; t2 > 0; t2 >>= 1) { if (j < t2) red[j] += red[j + t2]; __syncthreads(); }
    if (j == 0) g_btil[o] = red[0] + b1[o];
}

__global__ __launch_bounds__(256) void k_dot(const float* __restrict__ H2,
                                             const float* __restrict__ W3,
                                             const float* __restrict__ b3,
                                             float* __restrict__ out)
{
    int w = (blockIdx.x * blockDim.x + threadIdx.x) >> 5;
    int lane = threadIdx.x & 31;
    if (w >= NB) return;
    float4 h = ((const float4*)(H2 + (size_t)w * 128))[lane];
    float4 c = ((const float4*)W3)[lane];
    float s = h.x * c.x + h.y * c.y + h.z * c.z + h.w * c.w;
    for (int o = 16; o; o >>= 1) s += __shfl_xor_sync(0xffffffffu, s, o);
    if (lane == 0) out[w] = s + b3[0];
}

// ---------------- host ----------------
static inline int ceildiv(int a, int b) { return (a + b - 1) / b; }

extern "C" void kernel_launch(void* const* d_in, const int* in_sizes, int n_in,
                              void* d_out, int out_size)
{
    int fi, ii;
    if (in_sizes[0] == NE) { ii = 0; fi = 6; } else { fi = 0; ii = 15; }
    const float* emb_drug  = (const float*)d_in[fi + 0];
    const float* emb_dis   = (const float*)d_in[fi + 1];
    const float* conv_Wl   = (const float*)d_in[fi + 2];
    const float* conv_bl   = (const float*)d_in[fi + 3];
    const float* conv_Wr   = (const float*)d_in[fi + 4];
    const float* attn_Win  = (const float*)d_in[fi + 5];
    const float* attn_bin  = (const float*)d_in[fi + 6];
    const float* attn_Wout = (const float*)d_in[fi + 7];
    const float* attn_bout = (const float*)d_in[fi + 8];
    const float* mlp_W1    = (const float*)d_in[fi + 9];
    const float* mlp_b1    = (const float*)d_in[fi + 10];
    const float* mlp_W2    = (const float*)d_in[fi + 11];
    const float* mlp_b2    = (const float*)d_in[fi + 12];
    const float* mlp_W3    = (const float*)d_in[fi + 13];
    const float* mlp_b3    = (const float*)d_in[fi + 14];
    const int* src_d2di    = (const int*)d_in[ii + 0];
    const int* dst_d2di    = (const int*)d_in[ii + 1];
    const int* src_di2dr   = (const int*)d_in[ii + 2];
    const int* dst_di2dr   = (const int*)d_in[ii + 3];
    const int* drug_idx    = (const int*)d_in[ii + 4];
    const int* disease_idx = (const int*)d_in[ii + 5];
    float* out = (float*)d_out;

    void* p;
    cudaGetSymbolAddress(&p, g_aggc_dis);   float* aggc_dis   = (float*)p;
    cudaGetSymbolAddress(&p, g_aggc_drug);  float* aggc_drug  = (float*)p;
    cudaGetSymbolAddress(&p, g_head_dis);   int*   head_dis   = (int*)p;
    cudaGetSymbolAddress(&p, g_head_drug);  int*   head_drug  = (int*)p;
    cudaGetSymbolAddress(&p, g_next_dis);   int*   next_dis   = (int*)p;
    cudaGetSymbolAddress(&p, g_next_drug);  int*   next_drug  = (int*)p;
    cudaGetSymbolAddress(&p, g_dis_L1_0);   float* dis_L1_0   = (float*)p;
    cudaGetSymbolAddress(&p, g_dis_L1_1);   float* dis_L1_1   = (float*)p;
    cudaGetSymbolAddress(&p, g_drug_L1_0);  float* drug_L1_0  = (float*)p;
    cudaGetSymbolAddress(&p, g_drug_L1_1);  float* drug_L1_1  = (float*)p;
    cudaGetSymbolAddress(&p, g_drug_L2);    float* drug_L2    = (float*)p;
    cudaGetSymbolAddress(&p, g_dis_L2);     float* dis_L2     = (float*)p;
    cudaGetSymbolAddress(&p, g_l_dis_s0);   int* l_dis_s0     = (int*)p;
    cudaGetSymbolAddress(&p, g_l_dis_s1);   int* l_dis_s1     = (int*)p;
    cudaGetSymbolAddress(&p, g_l_dis_ag);   int* l_dis_ag     = (int*)p;
    cudaGetSymbolAddress(&p, g_l_drug_s0);  int* l_drug_s0    = (int*)p;
    cudaGetSymbolAddress(&p, g_l_drug_s1);  int* l_drug_s1    = (int*)p;
    cudaGetSymbolAddress(&p, g_l_drug_ag);  int* l_drug_ag    = (int*)p;
    cudaGetSymbolAddress(&p, g_s_dis_s0);   int* s_dis_s0     = (int*)p;
    cudaGetSymbolAddress(&p, g_s_drug_s1);  int* s_drug_s1    = (int*)p;
    cudaGetSymbolAddress(&p, g_a1_dis_s0);  int* a1_dis_s0    = (int*)p;
    cudaGetSymbolAddress(&p, g_a1_dis_s1);  int* a1_dis_s1    = (int*)p;
    cudaGetSymbolAddress(&p, g_a1_drug_s0); int* a1_drug_s0   = (int*)p;
    cudaGetSymbolAddress(&p, g_a1_drug_s1); int* a1_drug_s1   = (int*)p;
    cudaGetSymbolAddress(&p, g_gd);         int* gd           = (int*)p;
    cudaGetSymbolAddress(&p, g_gs);         int* gs           = (int*)p;
    cudaGetSymbolAddress(&p, g_ctr);        int* ctr          = (int*)p;
    cudaGetSymbolAddress(&p, g_Md);         float* Md         = (float*)p;
    cudaGetSymbolAddress(&p, g_Ms);         float* Ms         = (float*)p;
    cudaGetSymbolAddress(&p, g_btil);       float* btil       = (float*)p;
    cudaGetSymbolAddress(&p, g_H1);         float* H1         = (float*)p;
    cudaGetSymbolAddress(&p, g_H2);         float* H2         = (float*)p;

    auto woff = [](int s, int l, int et) { return (size_t)((s * 2 + l) * 2 + et) * 128 * 128; };
    auto boff = [](int s, int l, int et) { return (size_t)((s * 2 + l) * 2 + et) * 128; };

    // 1. init + mark + one-pass linked-list CSR + frontier from chains
    k_init<<<ceildiv(N_DRUG, 256), 256>>>();
    k_mark<<<ceildiv(NB, 256), 256>>>(drug_idx, disease_idx);
    k_link<<<ceildiv(2 * NE, 256), 256>>>(dst_d2di, dst_di2dr);
    k_frontier<<<dim3(ceildiv(NB, 256), 2), 256>>>(src_di2dr, src_d2di);
    // 2. L1 gather-mean (compact, ag-list order)
    k_gather<<<ceildiv(N_DIS * 32, 256), 256>>>(l_dis_ag, ctr + C_DIS_AG, head_dis, next_dis,
                                                src_d2di, nullptr, emb_drug, aggc_dis);
    k_gather<<<ceildiv(N_DRUG * 32, 256), 256>>>(l_drug_ag, ctr + C_DRUG_AG, head_drug, next_drug,
                                                 src_di2dr, nullptr, emb_dis, aggc_drug);
    // 3. per-row gather index composition
    k_compose<<<dim3(ceildiv(N_DRUG, 256), 6), 256>>>(drug_idx, disease_idx);
    // 4. L1 GEMMs
    k_gemm<<<ceildiv(N_DIS, TMR), 256>>>(ctr + C_DIS_S0, 0, aggc_dis, a1_dis_s0, emb_dis, l_dis_s0,
                        128, 256, conv_Wl + woff(0,0,0), conv_Wr + woff(0,0,0), conv_bl + boff(0,0,0),
                        dis_L1_0, 128, 1);
    k_gemm<<<ceildiv(NB, TMR), 256>>>(ctr + C_DIS_S1, 0, aggc_dis, a1_dis_s1, emb_dis, l_dis_s1,
                        128, 256, conv_Wl + woff(1,0,0), conv_Wr + woff(1,0,0), conv_bl + boff(1,0,0),
                        dis_L1_1, 128, 1);
    k_gemm<<<ceildiv(NB, TMR), 256>>>(ctr + C_DRUG_S0, 0, aggc_drug, a1_drug_s0, emb_drug, l_drug_s0,
                        128, 256, conv_Wl + woff(0,0,1), conv_Wr + woff(0,0,1), conv_bl + boff(0,0,1),
                        drug_L1_0, 128, 1);
    k_gemm<<<ceildiv(N_DRUG, TMR), 256>>>(ctr + C_DRUG_S1, 0, aggc_drug, a1_drug_s1, emb_drug, l_drug_s1,
                        128, 256, conv_Wl + woff(1,0,1), conv_Wr + woff(1,0,1), conv_bl + boff(1,0,1),
                        drug_L1_1, 128, 1);
    // 5. L2 gather-mean (targets only; reuse aggc buffers)
    k_gather<<<ceildiv(NB * 32, 256), 256>>>(l_drug_s0, ctr + C_DRUG_S0, head_drug, next_drug,
                                             src_di2dr, s_dis_s0, dis_L1_0, aggc_drug);
    k_gather<<<ceildiv(NB * 32, 256), 256>>>(l_dis_s1, ctr + C_DIS_S1, head_dis, next_dis,
                                             src_d2di, s_drug_s1, drug_L1_1, aggc_dis);
    // 6. L2 GEMMs (compact rows, same list order as their inputs)
    k_gemm<<<ceildiv(NB, TMR), 256>>>(ctr + C_DRUG_S0, 0, aggc_drug, nullptr, drug_L1_0, nullptr,
                        128, 256, conv_Wl + woff(0,1,1), conv_Wr + woff(0,1,1), conv_bl + boff(0,1,1),
                        drug_L2, 128, 1);
    k_gemm<<<ceildiv(NB, TMR), 256>>>(ctr + C_DIS_S1, 0, aggc_dis, nullptr, dis_L1_1, nullptr,
                        128, 256, conv_Wl + woff(1,1,0), conv_Wr + woff(1,1,0), conv_bl + boff(1,1,0),
                        dis_L2, 128, 1);
    // 7. fold degenerate MHA into MLP layer 1
    k_fold1<<<dim3(128, 2), 128>>>(attn_Win, attn_bin, attn_Wout, attn_bout);
    k_fold2<<<256, 128>>>(mlp_W1, mlp_b1);
    // 8. pair head
    k_gemm<<<dim3(ceildiv(NB, TMR), 2), 256>>>(nullptr, NB, drug_L2, gd, dis_L2, gs,
                        128, 256, Md, Ms, btil, H1, 256, 1);
    k_gemm<<<dim3(ceildiv(NB, TMR), 1), 256>>>(nullptr, NB, H1, nullptr, H1, nullptr,
                        256, 256, mlp_W2, mlp_W2, mlp_b2, H2, 128, 1);
    k_dot<<<ceildiv(NB * 32, 256), 256>>>(H2, mlp_W3, mlp_b3, out);
}

// round 11
// speedup vs baseline: 1.4412x; 1.0320x over previous
#include <cuda_runtime.h>
#include <cuda_bf16.h>
#include <cstdint>

#define N_DRUG 200000
#define N_DIS  100000
#define HDIM   128
#define NE     600000
#define NB     8192

#define C_DIS_S0  0
#define C_DIS_S1  1
#define C_DIS_AG  2
#define C_DRUG_S0 3
#define C_DRUG_S1 4
#define C_DRUG_AG 5

// ---------------- device scratch ----------------
__device__ float g_aggc_dis [(size_t)N_DIS  * HDIM];   // L1 agg compact (ag-list order); reused for L2 dis agg
__device__ float g_aggc_drug[(size_t)N_DRUG * HDIM];   // same for drugs; reused for L2 drug agg
__device__ int   g_head_dis [N_DIS];    // d2di edges chained by dis dst
__device__ int   g_head_drug[N_DRUG];   // di2dr edges chained by drug dst
__device__ int   g_next_dis [NE];
__device__ int   g_next_drug[NE];
__device__ float g_dis_L1_0 [(size_t)N_DIS  * HDIM];   // compact over l_dis_s0
__device__ float g_dis_L1_1 [(size_t)NB     * HDIM];   // compact over l_dis_s1
__device__ float g_drug_L1_0[(size_t)NB     * HDIM];   // compact over l_drug_s0
__device__ float g_drug_L1_1[(size_t)N_DRUG * HDIM];   // compact over l_drug_s1
__device__ float g_drug_L2 [(size_t)NB * HDIM];
__device__ float g_dis_L2  [(size_t)NB * HDIM];
__device__ int g_m_dis_s0[N_DIS],  g_m_dis_s1[N_DIS],  g_m_dis_ag[N_DIS];
__device__ int g_m_drug_s0[N_DRUG],g_m_drug_s1[N_DRUG],g_m_drug_ag[N_DRUG];
__device__ int g_l_dis_s0[N_DIS],  g_l_dis_s1[N_DIS],  g_l_dis_ag[N_DIS];
__device__ int g_l_drug_s0[N_DRUG],g_l_drug_s1[N_DRUG],g_l_drug_ag[N_DRUG];
__device__ int g_s_dis_s0[N_DIS],  g_s_dis_s1[N_DIS],  g_s_dis_ag[N_DIS];
__device__ int g_s_drug_s0[N_DRUG],g_s_drug_s1[N_DRUG],g_s_drug_ag[N_DRUG];
__device__ int g_a1_dis_s0[N_DIS], g_a1_dis_s1[NB], g_a1_drug_s0[NB], g_a1_drug_s1[N_DRUG];
__device__ int g_gd[NB], g_gs[NB];
__device__ int g_ctr[8];
__device__ float g_A0[HDIM*HDIM], g_A1[HDIM*HDIM], g_c0[HDIM], g_c1[HDIM];
__device__ float g_Md[256*HDIM], g_Ms[256*HDIM], g_btil[256];
__device__ float g_H1[(size_t)NB * 256];
__device__ float g_H2[(size_t)NB * HDIM];

// ---------------- init: masks + chain heads + counters ----------------
__global__ __launch_bounds__(256) void k_init()
{
    int i = blockIdx.x * blockDim.x + threadIdx.x;
    if (i < N_DIS) {
        g_m_dis_s0[i] = 0; g_m_dis_s1[i] = 0; g_m_dis_ag[i] = 0; g_head_dis[i] = -1;
    }
    if (i < N_DRUG) {
        g_m_drug_s0[i] = 0; g_m_drug_s1[i] = 0; g_m_drug_ag[i] = 0; g_head_drug[i] = -1;
    }
    if (i < 8) g_ctr[i] = 0;
}

// mark targets; record compact slots at claim time
__global__ __launch_bounds__(256) void k_mark(const int* __restrict__ drug_idx,
                                              const int* __restrict__ disease_idx)
{
    int i = blockIdx.x * blockDim.x + threadIdx.x;
    if (i >= NB) return;
    int d = drug_idx[i];
    if (atomicExch(&g_m_drug_s0[d], 1) == 0) {
        int p = atomicAdd(&g_ctr[C_DRUG_S0], 1); g_l_drug_s0[p] = d; g_s_drug_s0[d] = p;
    }
    if (atomicExch(&g_m_drug_ag[d], 1) == 0) {
        int p = atomicAdd(&g_ctr[C_DRUG_AG], 1); g_l_drug_ag[p] = d; g_s_drug_ag[d] = p;
    }
    int s = disease_idx[i];
    if (atomicExch(&g_m_dis_s1[s], 1) == 0) {
        int p = atomicAdd(&g_ctr[C_DIS_S1], 1); g_l_dis_s1[p] = s; g_s_dis_s1[s] = p;
    }
    if (atomicExch(&g_m_dis_ag[s], 1) == 0) {
        int p = atomicAdd(&g_ctr[C_DIS_AG], 1); g_l_dis_ag[p] = s; g_s_dis_ag[s] = p;
    }
}

// fused: one-pass linked-list CSR + frontier marking.
// d2di edge (dst=dis): link into dis chain; if dst is a dis_s1 target, its drug src
// joins drug_s1 (+ag). di2dr edge (dst=drug): link into drug chain; if dst is a
// drug_s0 target, its dis src joins dis_s0 (+ag). Masks were written by k_mark.
__global__ __launch_bounds__(256) void k_link(const int* __restrict__ src_d2di,
                                              const int* __restrict__ dst_d2di,
                                              const int* __restrict__ src_di2dr,
                                              const int* __restrict__ dst_di2dr)
{
    int e = blockIdx.x * blockDim.x + threadIdx.x;
    if (e < NE) {
        int d = dst_d2di[e];                 // disease dst
        g_next_dis[e] = atomicExch(&g_head_dis[d], e);
        if (g_m_dis_s1[d]) {
            int s = __ldg(src_d2di + e);     // drug neighbor of a target disease
            if (atomicExch(&g_m_drug_s1[s], 1) == 0) {
                int p = atomicAdd(&g_ctr[C_DRUG_S1], 1); g_l_drug_s1[p] = s; g_s_drug_s1[s] = p;
            }
            if (atomicExch(&g_m_drug_ag[s], 1) == 0) {
                int p = atomicAdd(&g_ctr[C_DRUG_AG], 1); g_l_drug_ag[p] = s; g_s_drug_ag[s] = p;
            }
        }
    } else if (e < 2 * NE) {
        int e2 = e - NE;
        int d = dst_di2dr[e2];               // drug dst
        g_next_drug[e2] = atomicExch(&g_head_drug[d], e2);
        if (g_m_drug_s0[d]) {
            int s = __ldg(src_di2dr + e2);   // disease neighbor of a target drug
            if (atomicExch(&g_m_dis_s0[s], 1) == 0) {
                int p = atomicAdd(&g_ctr[C_DIS_S0], 1); g_l_dis_s0[p] = s; g_s_dis_s0[s] = p;
            }
            if (atomicExch(&g_m_dis_ag[s], 1) == 0) {
                int p = atomicAdd(&g_ctr[C_DIS_AG], 1); g_l_dis_ag[p] = s; g_s_dis_ag[s] = p;
            }
        }
    }
}

// warp-per-node chain-walk gather-mean: out[r] = mean_{e in chain(node)} X[map(src[e])]
__global__ __launch_bounds__(256) void k_gather(const int* __restrict__ list,
                                                const int* __restrict__ cntp,
                                                const int* __restrict__ head,
                                                const int* __restrict__ next,
                                                const int* __restrict__ srcArr,
                                                const int* __restrict__ slotmap,
                                                const float* __restrict__ X,
                                                float* __restrict__ out)
{
    int w = (blockIdx.x * blockDim.x + threadIdx.x) >> 5;
    int lane = threadIdx.x & 31;
    if (w >= *cntp) return;
    int node = list[w];
    float4 acc = make_float4(0.f, 0.f, 0.f, 0.f);
    int n = 0;
    int e = head[node];
    while (e >= 0) {
        int nx = __ldg(next + e);
        int s = __ldg(srcArr + e);
        int row = slotmap ? slotmap[s] : s;
        float4 v = ((const float4*)(X + (size_t)row * HDIM))[lane];
        acc.x += v.x; acc.y += v.y; acc.z += v.z; acc.w += v.w;
        ++n;
        e = nx;
    }
    float inv = n ? 1.f / (float)n : 0.f;
    acc.x *= inv; acc.y *= inv; acc.z *= inv; acc.w *= inv;
    ((float4*)(out + (size_t)w * HDIM))[lane] = acc;
}

// compose per-row gather indices (6 segments via blockIdx.y)
__global__ __launch_bounds__(256) void k_compose(const int* __restrict__ drug_idx,
                                                 const int* __restrict__ disease_idx)
{
    int y = blockIdx.y;
    int i = blockIdx.x * blockDim.x + threadIdx.x;
    switch (y) {
    case 0: if (i < g_ctr[C_DIS_S0])  g_a1_dis_s0[i]  = g_s_dis_ag[g_l_dis_s0[i]];   break;
    case 1: if (i < g_ctr[C_DIS_S1])  g_a1_dis_s1[i]  = g_s_dis_ag[g_l_dis_s1[i]];   break;
    case 2: if (i < g_ctr[C_DRUG_S0]) g_a1_drug_s0[i] = g_s_drug_ag[g_l_drug_s0[i]]; break;
    case 3: if (i < g_ctr[C_DRUG_S1]) g_a1_drug_s1[i] = g_s_drug_ag[g_l_drug_s1[i]]; break;
    case 4: if (i < NB)               g_gd[i]         = g_s_drug_s0[drug_idx[i]];    break;
    case 5: if (i < NB)               g_gs[i]         = g_s_dis_s1[disease_idx[i]];  break;
    }
}

// ---------------- tiled SGEMM with packed f32x2 FMA ----------------
#define TMR 64
#define KCH 32

#define FMA2(d, a, b) asm("fma.rn.f32x2 %0, %1, %2, %0;" : "+l"(d) : "l"(a), "l"(b))

__global__ __launch_bounds__(256) void k_gemm(
    const int* __restrict__ rowcnt, int nfixed,
    const float* __restrict__ X1, const int* __restrict__ g1,
    const float* __restrict__ X2, const int* __restrict__ g2,
    int K1, int K,
    const float* __restrict__ Wa, const float* __restrict__ Wb,
    const float* __restrict__ bias,
    float* __restrict__ out, int Nout, int relu)
{
    __shared__ float As[TMR][KCH + 1];
    __shared__ float Ws[KCH][128];
    __shared__ int   s_a1[TMR], s_a2[TMR], s_ok[TMR];

    int nr = rowcnt ? *rowcnt : nfixed;
    int row0 = blockIdx.x * TMR;
    if (row0 >= nr) return;
    int t = threadIdx.x;
    int n0 = blockIdx.y * 128;

    if (t < TMR) {
        int r = row0 + t;
        int ok = r < nr;
        s_a1[t] = ok ? (g1 ? g1[r] : r) : 0;
        s_a2[t] = ok ? (g2 ? g2[r] : r) : 0;
        s_ok[t] = ok;
    }
    __syncthreads();

    unsigned long long acc2[4][4];
#pragma unroll
    for (int i = 0; i < 4; ++i)
#pragma unroll
        for (int j = 0; j < 4; ++j) acc2[i][j] = 0ULL;

    int tx = t & 15;
    int ty = t >> 4;
    int K2 = K - K1;
    int nch = K / KCH;

    for (int c = 0; c < nch; ++c) {
        int kb = c * KCH;
        {   // A tile
            int i  = t >> 2;
            int k0 = (t & 3) * 8;
            float4 v0 = make_float4(0.f, 0.f, 0.f, 0.f), v1 = v0;
            if (s_ok[i]) {
                int k = kb + k0;
                if (k < K1) {
                    const float4* p = (const float4*)(X1 + (size_t)s_a1[i] * K1 + k);
                    v0 = p[0]; v1 = p[1];
                } else {
                    const float4* p = (const float4*)(X2 + (size_t)s_a2[i] * K2 + (k - K1));
                    v0 = p[0]; v1 = p[1];
                }
            }
            As[i][k0+0] = v0.x; As[i][k0+1] = v0.y; As[i][k0+2] = v0.z; As[i][k0+3] = v0.w;
            As[i][k0+4] = v1.x; As[i][k0+5] = v1.y; As[i][k0+6] = v1.z; As[i][k0+7] = v1.w;
        }
        {   // W tile
            int n  = t >> 1;
            int k0 = (t & 1) * 16;
            int gk = kb + k0;
            const float* wp = (gk < K1) ? (Wa + (size_t)(n0 + n) * K1 + gk)
                                        : (Wb + (size_t)(n0 + n) * K2 + (gk - K1));
#pragma unroll
            for (int j = 0; j < 16; j += 4) {
                float4 w = *(const float4*)(wp + j);
                Ws[k0+j+0][n] = w.x; Ws[k0+j+1][n] = w.y;
                Ws[k0+j+2][n] = w.z; Ws[k0+j+3][n] = w.w;
            }
        }
        __syncthreads();
#pragma unroll
        for (int kk = 0; kk < KCH; ++kk) {
            ulonglong2 wA = ((const ulonglong2*)&Ws[kk][tx * 8])[0];
            ulonglong2 wB = ((const ulonglong2*)&Ws[kk][tx * 8])[1];
#pragma unroll
            for (int i = 0; i < 4; ++i) {
                unsigned au = __float_as_uint(As[ty * 4 + i][kk]);
                unsigned long long ap;
                asm("mov.b64 %0, {%1, %1};" : "=l"(ap) : "r"(au));
                FMA2(acc2[i][0], ap, wA.x);
                FMA2(acc2[i][1], ap, wA.y);
                FMA2(acc2[i][2], ap, wB.x);
                FMA2(acc2[i][3], ap, wB.y);
            }
        }
        __syncthreads();
    }

    float b[8];
#pragma unroll
    for (int j = 0; j < 8; ++j) b[j] = bias[n0 + tx * 8 + j];
#pragma unroll
    for (int i = 0; i < 4; ++i) {
        int ri = ty * 4 + i;
        if (!s_ok[ri]) continue;
        float ov[8];
#pragma unroll
        for (int p2 = 0; p2 < 4; ++p2) {
            unsigned lo, hi;
            asm("mov.b64 {%0, %1}, %2;" : "=r"(lo), "=r"(hi) : "l"(acc2[i][p2]));
            ov[2*p2]   = __uint_as_float(lo) + b[2*p2];
            ov[2*p2+1] = __uint_as_float(hi) + b[2*p2+1];
        }
        if (relu) {
#pragma unroll
            for (int j = 0; j < 8; ++j) ov[j] = fmaxf(ov[j], 0.f);
        }
        float* op = out + (size_t)(row0 + ri) * Nout + n0 + tx * 8;
        ((float4*)op)[0] = make_float4(ov[0], ov[1], ov[2], ov[3]);
        ((float4*)op)[1] = make_float4(ov[4], ov[5], ov[6], ov[7]);
    }
}

// fold attention (len-1 kv => softmax == 1): A_m = Wout_m @ Wv_m, c_m = Wout_m@bv_m + bout_m
__global__ __launch_bounds__(128) void k_fold1(const float* __restrict__ Win,
                                               const float* __restrict__ bin,
                                               const float* __restrict__ Wout,
                                               const float* __restrict__ bout)
{
    int m = blockIdx.y;
    int tt = blockIdx.x;
    int j = threadIdx.x;
    const float* Wv = Win + (size_t)m * 384 * 128 + 256 * 128;
    const float* Wo = Wout + (size_t)m * 128 * 128;
    const float* bv = bin + m * 384 + 256;
    const float* bo = bout + m * 128;
    const float* worow = Wo + (size_t)tt * 128;
    float s = 0.f;
    for (int u = 0; u < 128; ++u) s += worow[u] * Wv[(size_t)u * 128 + j];
    (m == 0 ? g_A0 : g_A1)[tt * 128 + j] = s;
    __shared__ float red[128];
    red[j] = worow[j] * bv[j];
    __syncthreads();
    for (int o = 64; o > 0; o >>= 1) { if (j < o) red[j] += red[j + o]; __syncthreads(); }
    if (j == 0) (m == 0 ? g_c0 : g_c1)[tt] = red[0] + bo[tt];
}

// fold attention affine maps into mlp_W1: h1 = relu(Md*de + Ms*se + btil)
__global__ __launch_bounds__(128) void k_fold2(const float* __restrict__ W1,
                                               const float* __restrict__ b1)
{
    int o = blockIdx.x, j = threadIdx.x;
    const float* wrow = W1 + (size_t)o * 512;
    float md = wrow[j];
    float ms = wrow[128 + j];
    for (int tt = 0; tt < 128; ++tt) {
        ms += wrow[256 + tt] * g_A0[tt * 128 + j];
        md += wrow[384 + tt] * g_A1[tt * 128 + j];
    }
    g_Md[o * 128 + j] = md;
    g_Ms[o * 128 + j] = ms;
    __shared__ float red[128];
    red[j] = wrow[256 + j] * g_c0[j] + wrow[384 + j] * g_c1[j];
    __syncthreads();
    for (int t2 = 64; t2 > 0; t2 >>= 1) { if (j < t2) red[j] += red[j + t2]; __syncthreads(); }
    if (j == 0) g_btil[o] = red[0] + b1[o];
}

__global__ __launch_bounds__(256) void k_dot(const float* __restrict__ H2,
                                             const float* __restrict__ W3,
                                             const float* __restrict__ b3,
                                             float* __restrict__ out)
{
    int w = (blockIdx.x * blockDim.x + threadIdx.x) >> 5;
    int lane = threadIdx.x & 31;
    if (w >= NB) return;
    float4 h = ((const float4*)(H2 + (size_t)w * 128))[lane];
    float4 c = ((const float4*)W3)[lane];
    float s = h.x * c.x + h.y * c.y + h.z * c.z + h.w * c.w;
    for (int o = 16; o; o >>= 1) s += __shfl_xor_sync(0xffffffffu, s, o);
    if (lane == 0) out[w] = s + b3[0];
}

// ---------------- host ----------------
static inline int ceildiv(int a, int b) { return (a + b - 1) / b; }

extern "C" void kernel_launch(void* const* d_in, const int* in_sizes, int n_in,
                              void* d_out, int out_size)
{
    int fi, ii;
    if (in_sizes[0] == NE) { ii = 0; fi = 6; } else { fi = 0; ii = 15; }
    const float* emb_drug  = (const float*)d_in[fi + 0];
    const float* emb_dis   = (const float*)d_in[fi + 1];
    const float* conv_Wl   = (const float*)d_in[fi + 2];
    const float* conv_bl   = (const float*)d_in[fi + 3];
    const float* conv_Wr   = (const float*)d_in[fi + 4];
    const float* attn_Win  = (const float*)d_in[fi + 5];
    const float* attn_bin  = (const float*)d_in[fi + 6];
    const float* attn_Wout = (const float*)d_in[fi + 7];
    const float* attn_bout = (const float*)d_in[fi + 8];
    const float* mlp_W1    = (const float*)d_in[fi + 9];
    const float* mlp_b1    = (const float*)d_in[fi + 10];
    const float* mlp_W2    = (const float*)d_in[fi + 11];
    const float* mlp_b2    = (const float*)d_in[fi + 12];
    const float* mlp_W3    = (const float*)d_in[fi + 13];
    const float* mlp_b3    = (const float*)d_in[fi + 14];
    const int* src_d2di    = (const int*)d_in[ii + 0];
    const int* dst_d2di    = (const int*)d_in[ii + 1];
    const int* src_di2dr   = (const int*)d_in[ii + 2];
    const int* dst_di2dr   = (const int*)d_in[ii + 3];
    const int* drug_idx    = (const int*)d_in[ii + 4];
    const int* disease_idx = (const int*)d_in[ii + 5];
    float* out = (float*)d_out;

    void* p;
    cudaGetSymbolAddress(&p, g_aggc_dis);   float* aggc_dis   = (float*)p;
    cudaGetSymbolAddress(&p, g_aggc_drug);  float* aggc_drug  = (float*)p;
    cudaGetSymbolAddress(&p, g_head_dis);   int*   head_dis   = (int*)p;
    cudaGetSymbolAddress(&p, g_head_drug);  int*   head_drug  = (int*)p;
    cudaGetSymbolAddress(&p, g_next_dis);   int*   next_dis   = (int*)p;
    cudaGetSymbolAddress(&p, g_next_drug);  int*   next_drug  = (int*)p;
    cudaGetSymbolAddress(&p, g_dis_L1_0);   float* dis_L1_0   = (float*)p;
    cudaGetSymbolAddress(&p, g_dis_L1_1);   float* dis_L1_1   = (float*)p;
    cudaGetSymbolAddress(&p, g_drug_L1_0);  float* drug_L1_0  = (float*)p;
    cudaGetSymbolAddress(&p, g_drug_L1_1);  float* drug_L1_1  = (float*)p;
    cudaGetSymbolAddress(&p, g_drug_L2);    float* drug_L2    = (float*)p;
    cudaGetSymbolAddress(&p, g_dis_L2);     float* dis_L2     = (float*)p;
    cudaGetSymbolAddress(&p, g_l_dis_s0);   int* l_dis_s0     = (int*)p;
    cudaGetSymbolAddress(&p, g_l_dis_s1);   int* l_dis_s1     = (int*)p;
    cudaGetSymbolAddress(&p, g_l_dis_ag);   int* l_dis_ag     = (int*)p;
    cudaGetSymbolAddress(&p, g_l_drug_s0);  int* l_drug_s0    = (int*)p;
    cudaGetSymbolAddress(&p, g_l_drug_s1);  int* l_drug_s1    = (int*)p;
    cudaGetSymbolAddress(&p, g_l_drug_ag);  int* l_drug_ag    = (int*)p;
    cudaGetSymbolAddress(&p, g_s_dis_s0);   int* s_dis_s0     = (int*)p;
    cudaGetSymbolAddress(&p, g_s_drug_s1);  int* s_drug_s1    = (int*)p;
    cudaGetSymbolAddress(&p, g_a1_dis_s0);  int* a1_dis_s0    = (int*)p;
    cudaGetSymbolAddress(&p, g_a1_dis_s1);  int* a1_dis_s1    = (int*)p;
    cudaGetSymbolAddress(&p, g_a1_drug_s0); int* a1_drug_s0   = (int*)p;
    cudaGetSymbolAddress(&p, g_a1_drug_s1); int* a1_drug_s1   = (int*)p;
    cudaGetSymbolAddress(&p, g_gd);         int* gd           = (int*)p;
    cudaGetSymbolAddress(&p, g_gs);         int* gs           = (int*)p;
    cudaGetSymbolAddress(&p, g_ctr);        int* ctr          = (int*)p;
    cudaGetSymbolAddress(&p, g_Md);         float* Md         = (float*)p;
    cudaGetSymbolAddress(&p, g_Ms);         float* Ms         = (float*)p;
    cudaGetSymbolAddress(&p, g_btil);       float* btil       = (float*)p;
    cudaGetSymbolAddress(&p, g_H1);         float* H1         = (float*)p;
    cudaGetSymbolAddress(&p, g_H2);         float* H2         = (float*)p;

    auto woff = [](int s, int l, int et) { return (size_t)((s * 2 + l) * 2 + et) * 128 * 128; };
    auto boff = [](int s, int l, int et) { return (size_t)((s * 2 + l) * 2 + et) * 128; };

    // 1. init + mark + fused link/frontier
    k_init<<<ceildiv(N_DRUG, 256), 256>>>();
    k_mark<<<ceildiv(NB, 256), 256>>>(drug_idx, disease_idx);
    k_link<<<ceildiv(2 * NE, 256), 256>>>(src_d2di, dst_d2di, src_di2dr, dst_di2dr);
    // 2. L1 gather-mean (compact, ag-list order)
    k_gather<<<ceildiv(N_DIS * 32, 256), 256>>>(l_dis_ag, ctr + C_DIS_AG, head_dis, next_dis,
                                                src_d2di, nullptr, emb_drug, aggc_dis);
    k_gather<<<ceildiv(N_DRUG * 32, 256), 256>>>(l_drug_ag, ctr + C_DRUG_AG, head_drug, next_drug,
                                                 src_di2dr, nullptr, emb_dis, aggc_drug);
    // 3. per-row gather index composition
    k_compose<<<dim3(ceildiv(N_DRUG, 256), 6), 256>>>(drug_idx, disease_idx);
    // 4. L1 GEMMs
    k_gemm<<<ceildiv(N_DIS, TMR), 256>>>(ctr + C_DIS_S0, 0, aggc_dis, a1_dis_s0, emb_dis, l_dis_s0,
                        128, 256, conv_Wl + woff(0,0,0), conv_Wr + woff(0,0,0), conv_bl + boff(0,0,0),
                        dis_L1_0, 128, 1);
    k_gemm<<<ceildiv(NB, TMR), 256>>>(ctr + C_DIS_S1, 0, aggc_dis, a1_dis_s1, emb_dis, l_dis_s1,
                        128, 256, conv_Wl + woff(1,0,0), conv_Wr + woff(1,0,0), conv_bl + boff(1,0,0),
                        dis_L1_1, 128, 1);
    k_gemm<<<ceildiv(NB, TMR), 256>>>(ctr + C_DRUG_S0, 0, aggc_drug, a1_drug_s0, emb_drug, l_drug_s0,
                        128, 256, conv_Wl + woff(0,0,1), conv_Wr + woff(0,0,1), conv_bl + boff(0,0,1),
                        drug_L1_0, 128, 1);
    k_gemm<<<ceildiv(N_DRUG, TMR), 256>>>(ctr + C_DRUG_S1, 0, aggc_drug, a1_drug_s1, emb_drug, l_drug_s1,
                        128, 256, conv_Wl + woff(1,0,1), conv_Wr + woff(1,0,1), conv_bl + boff(1,0,1),
                        drug_L1_1, 128, 1);
    // 5. L2 gather-mean (targets only; reuse aggc buffers)
    k_gather<<<ceildiv(NB * 32, 256), 256>>>(l_drug_s0, ctr + C_DRUG_S0, head_drug, next_drug,
                                             src_di2dr, s_dis_s0, dis_L1_0, aggc_drug);
    k_gather<<<ceildiv(NB * 32, 256), 256>>>(l_dis_s1, ctr + C_DIS_S1, head_dis, next_dis,
                                             src_d2di, s_drug_s1, drug_L1_1, aggc_dis);
    // 6. L2 GEMMs (compact rows, same list order as their inputs)
    k_gemm<<<ceildiv(NB, TMR), 256>>>(ctr + C_DRUG_S0, 0, aggc_drug, nullptr, drug_L1_0, nullptr,
                        128, 256, conv_Wl + woff(0,1,1), conv_Wr + woff(0,1,1), conv_bl + boff(0,1,1),
                        drug_L2, 128, 1);
    k_gemm<<<ceildiv(NB, TMR), 256>>>(ctr + C_DIS_S1, 0, aggc_dis, nullptr, dis_L1_1, nullptr,
                        128, 256, conv_Wl + woff(1,1,0), conv_Wr + woff(1,1,0), conv_bl + boff(1,1,0),
                        dis_L2, 128, 1);
    // 7. fold degenerate MHA into MLP layer 1
    k_fold1<<<dim3(128, 2), 128>>>(attn_Win, attn_bin, attn_Wout, attn_bout);
    k_fold2<<<256, 128>>>(mlp_W1, mlp_b1);
    // 8. pair head
    k_gemm<<<dim3(ceildiv(NB, TMR), 2), 256>>>(nullptr, NB, drug_L2, gd, dis_L2, gs,
                        128, 256, Md, Ms, btil, H1, 256, 1);
    k_gemm<<<dim3(ceildiv(NB, TMR), 1), 256>>>(nullptr, NB, H1, nullptr, H1, nullptr,
                        256, 256, mlp_W2, mlp_W2, mlp_b2, H2, 128, 1);
    k_dot<<<ceildiv(NB * 32, 256), 256>>>(H2, mlp_W3, mlp_b3, out);
}

// round 13
// speedup vs baseline: 1.6890x; 1.1720x over previous
#include <cuda_runtime.h>
#include <cuda_bf16.h>
#include <cstdint>

#define N_DRUG 200000
#define N_DIS  100000
#define HDIM   128
#define NE     600000
#define NB     8192

#define C_DIS_S0  0
#define C_DIS_S1  1
#define C_DIS_AG  2
#define C_DRUG_S0 3
#define C_DRUG_S1 4
#define C_DRUG_AG 5

#define TMR 64
#define KCH 32
#define NBLK_DIS  ((N_DIS  + TMR - 1) / TMR)   // 1563
#define NBLK_NB   ((NB     + TMR - 1) / TMR)   // 128
#define NBLK_DRUG ((N_DRUG + TMR - 1) / TMR)   // 3125
#define NBLK_L1   (NBLK_DIS + 2 * NBLK_NB + NBLK_DRUG)

// ---------------- device scratch ----------------
__device__ float g_aggc_dis [(size_t)N_DIS  * HDIM];
__device__ float g_aggc_drug[(size_t)N_DRUG * HDIM];
__device__ int   g_head_dis [N_DIS];
__device__ int   g_head_drug[N_DRUG];
__device__ int   g_next_dis [NE];
__device__ int   g_next_drug[NE];
__device__ float g_dis_L1_0 [(size_t)N_DIS  * HDIM];
__device__ float g_dis_L1_1 [(size_t)NB     * HDIM];
__device__ float g_drug_L1_0[(size_t)NB     * HDIM];
__device__ float g_drug_L1_1[(size_t)N_DRUG * HDIM];
__device__ float g_drug_L2 [(size_t)NB * HDIM];
__device__ float g_dis_L2  [(size_t)NB * HDIM];
__device__ int g_m_dis_s0[N_DIS],  g_m_dis_s1[N_DIS],  g_m_dis_ag[N_DIS];
__device__ int g_m_drug_s0[N_DRUG],g_m_drug_s1[N_DRUG],g_m_drug_ag[N_DRUG];
__device__ int g_l_dis_s0[N_DIS],  g_l_dis_s1[N_DIS],  g_l_dis_ag[N_DIS];
__device__ int g_l_drug_s0[N_DRUG],g_l_drug_s1[N_DRUG],g_l_drug_ag[N_DRUG];
__device__ int g_s_dis_s0[N_DIS],  g_s_dis_s1[N_DIS],  g_s_dis_ag[N_DIS];
__device__ int g_s_drug_s0[N_DRUG],g_s_drug_s1[N_DRUG],g_s_drug_ag[N_DRUG];
__device__ int g_a1_dis_s0[N_DIS], g_a1_dis_s1[NB], g_a1_drug_s0[NB], g_a1_drug_s1[N_DRUG];
__device__ int g_gd[NB], g_gs[NB];
__device__ int g_ctr[8];
__device__ float g_A0[HDIM*HDIM], g_A1[HDIM*HDIM], g_c0[HDIM], g_c1[HDIM];
__device__ float g_Md[256*HDIM], g_Ms[256*HDIM], g_btil[256];
__device__ float g_H1[(size_t)NB * 256];
__device__ float g_H2[(size_t)NB * HDIM];

// ---------------- init ----------------
__global__ __launch_bounds__(256) void k_init()
{
    int i = blockIdx.x * blockDim.x + threadIdx.x;
    if (i < N_DIS) {
        g_m_dis_s0[i] = 0; g_m_dis_s1[i] = 0; g_m_dis_ag[i] = 0; g_head_dis[i] = -1;
    }
    if (i < N_DRUG) {
        g_m_drug_s0[i] = 0; g_m_drug_s1[i] = 0; g_m_drug_ag[i] = 0; g_head_drug[i] = -1;
    }
    if (i < 8) g_ctr[i] = 0;
}

// mark targets; record compact slots at claim time
__global__ __launch_bounds__(256) void k_mark(const int* __restrict__ drug_idx,
                                              const int* __restrict__ disease_idx)
{
    int i = blockIdx.x * blockDim.x + threadIdx.x;
    if (i >= NB) return;
    int d = drug_idx[i];
    if (atomicExch(&g_m_drug_s0[d], 1) == 0) {
        int p = atomicAdd(&g_ctr[C_DRUG_S0], 1); g_l_drug_s0[p] = d; g_s_drug_s0[d] = p;
    }
    if (atomicExch(&g_m_drug_ag[d], 1) == 0) {
        int p = atomicAdd(&g_ctr[C_DRUG_AG], 1); g_l_drug_ag[p] = d; g_s_drug_ag[d] = p;
    }
    int s = disease_idx[i];
    if (atomicExch(&g_m_dis_s1[s], 1) == 0) {
        int p = atomicAdd(&g_ctr[C_DIS_S1], 1); g_l_dis_s1[p] = s; g_s_dis_s1[s] = p;
    }
    if (atomicExch(&g_m_dis_ag[s], 1) == 0) {
        int p = atomicAdd(&g_ctr[C_DIS_AG], 1); g_l_dis_ag[p] = s; g_s_dis_ag[s] = p;
    }
}

// fused: one-pass linked-list CSR + frontier marking
__global__ __launch_bounds__(256) void k_link(const int* __restrict__ src_d2di,
                                              const int* __restrict__ dst_d2di,
                                              const int* __restrict__ src_di2dr,
                                              const int* __restrict__ dst_di2dr)
{
    int e = blockIdx.x * blockDim.x + threadIdx.x;
    if (e < NE) {
        int d = dst_d2di[e];
        g_next_dis[e] = atomicExch(&g_head_dis[d], e);
        if (g_m_dis_s1[d]) {
            int s = __ldg(src_d2di + e);
            if (atomicExch(&g_m_drug_s1[s], 1) == 0) {
                int p = atomicAdd(&g_ctr[C_DRUG_S1], 1); g_l_drug_s1[p] = s; g_s_drug_s1[s] = p;
            }
            if (atomicExch(&g_m_drug_ag[s], 1) == 0) {
                int p = atomicAdd(&g_ctr[C_DRUG_AG], 1); g_l_drug_ag[p] = s; g_s_drug_ag[s] = p;
            }
        }
    } else if (e < 2 * NE) {
        int e2 = e - NE;
        int d = dst_di2dr[e2];
        g_next_drug[e2] = atomicExch(&g_head_drug[d], e2);
        if (g_m_drug_s0[d]) {
            int s = __ldg(src_di2dr + e2);
            if (atomicExch(&g_m_dis_s0[s], 1) == 0) {
                int p = atomicAdd(&g_ctr[C_DIS_S0], 1); g_l_dis_s0[p] = s; g_s_dis_s0[s] = p;
            }
            if (atomicExch(&g_m_dis_ag[s], 1) == 0) {
                int p = atomicAdd(&g_ctr[C_DIS_AG], 1); g_l_dis_ag[p] = s; g_s_dis_ag[s] = p;
            }
        }
    }
}

// warp-per-node chain-walk gather-mean body
__device__ __forceinline__ void gather_body(int w, int lane,
                                            const int* __restrict__ list,
                                            const int* __restrict__ cntp,
                                            const int* __restrict__ head,
                                            const int* __restrict__ next,
                                            const int* __restrict__ srcArr,
                                            const int* __restrict__ slotmap,
                                            const float* __restrict__ X,
                                            float* __restrict__ out)
{
    if (w >= *cntp) return;
    int node = list[w];
    float4 acc = make_float4(0.f, 0.f, 0.f, 0.f);
    int n = 0;
    int e = head[node];
    while (e >= 0) {
        int nx = __ldg(next + e);
        int s = __ldg(srcArr + e);
        int row = slotmap ? slotmap[s] : s;
        float4 v = ((const float4*)(X + (size_t)row * HDIM))[lane];
        acc.x += v.x; acc.y += v.y; acc.z += v.z; acc.w += v.w;
        ++n;
        e = nx;
    }
    float inv = n ? 1.f / (float)n : 0.f;
    acc.x *= inv; acc.y *= inv; acc.z *= inv; acc.w *= inv;
    ((float4*)(out + (size_t)w * HDIM))[lane] = acc;
}

// merged pair of gathers (blockIdx.y selects parameter set)
__global__ __launch_bounds__(256) void k_gather2(
    const int* l0, const int* c0, const int* h0, const int* n0p, const int* s0, const int* sm0, const float* X0, float* o0,
    const int* l1, const int* c1, const int* h1, const int* n1p, const int* s1, const int* sm1, const float* X1, float* o1)
{
    int w = (blockIdx.x * blockDim.x + threadIdx.x) >> 5;
    int lane = threadIdx.x & 31;
    if (blockIdx.y == 0)
        gather_body(w, lane, l0, c0, h0, n0p, s0, sm0, X0, o0);
    else
        gather_body(w, lane, l1, c1, h1, n1p, s1, sm1, X1, o1);
}

// compose per-row gather indices (6 segments via blockIdx.y)
__global__ __launch_bounds__(256) void k_compose(const int* __restrict__ drug_idx,
                                                 const int* __restrict__ disease_idx)
{
    int y = blockIdx.y;
    int i = blockIdx.x * blockDim.x + threadIdx.x;
    switch (y) {
    case 0: if (i < g_ctr[C_DIS_S0])  g_a1_dis_s0[i]  = g_s_dis_ag[g_l_dis_s0[i]];   break;
    case 1: if (i < g_ctr[C_DIS_S1])  g_a1_dis_s1[i]  = g_s_dis_ag[g_l_dis_s1[i]];   break;
    case 2: if (i < g_ctr[C_DRUG_S0]) g_a1_drug_s0[i] = g_s_drug_ag[g_l_drug_s0[i]]; break;
    case 3: if (i < g_ctr[C_DRUG_S1]) g_a1_drug_s1[i] = g_s_drug_ag[g_l_drug_s1[i]]; break;
    case 4: if (i < NB)               g_gd[i]         = g_s_drug_s0[drug_idx[i]];    break;
    case 5: if (i < NB)               g_gs[i]         = g_s_dis_s1[disease_idx[i]];  break;
    }
}

// ---------------- tiled SGEMM with packed f32x2 FMA ----------------
#define FMA2(d, a, b) asm("fma.rn.f32x2 %0, %1, %2, %0;" : "+l"(d) : "l"(a), "l"(b))

template<int K1, int K>
__device__ __forceinline__ void gemm_body(
    int rb, int n0, int nr,
    const float* __restrict__ X1, const int* __restrict__ g1,
    const float* __restrict__ X2, const int* __restrict__ g2,
    const float* __restrict__ Wa, const float* __restrict__ Wb,
    const float* __restrict__ bias,
    float* __restrict__ out, int Nout, int relu)
{
    __shared__ float As[TMR][KCH + 1];
    __shared__ float Ws[KCH][128];
    __shared__ int   s_a1[TMR], s_a2[TMR], s_ok[TMR];

    int row0 = rb * TMR;
    int t = threadIdx.x;

    if (t < TMR) {
        int r = row0 + t;
        int ok = r < nr;
        s_a1[t] = ok ? (g1 ? g1[r] : r) : 0;
        s_a2[t] = ok ? (g2 ? g2[r] : r) : 0;
        s_ok[t] = ok;
    }
    __syncthreads();

    unsigned long long acc2[4][4];
#pragma unroll
    for (int i = 0; i < 4; ++i)
#pragma unroll
        for (int j = 0; j < 4; ++j) acc2[i][j] = 0ULL;

    int tx = t & 15;
    int ty = t >> 4;
    constexpr int K2 = K - K1;
    constexpr int NCH = K / KCH;

#pragma unroll
    for (int c = 0; c < NCH; ++c) {
        int kb = c * KCH;
        {   // A tile
            int i  = t >> 2;
            int k0 = (t & 3) * 8;
            float4 v0 = make_float4(0.f, 0.f, 0.f, 0.f), v1 = v0;
            if (s_ok[i]) {
                int k = kb + k0;
                if (K2 == 0 || k < K1) {
                    const float4* p = (const float4*)(X1 + (size_t)s_a1[i] * K1 + k);
                    v0 = p[0]; v1 = p[1];
                } else {
                    const float4* p = (const float4*)(X2 + (size_t)s_a2[i] * (K2 ? K2 : 1) + (k - K1));
                    v0 = p[0]; v1 = p[1];
                }
            }
            As[i][k0+0] = v0.x; As[i][k0+1] = v0.y; As[i][k0+2] = v0.z; As[i][k0+3] = v0.w;
            As[i][k0+4] = v1.x; As[i][k0+5] = v1.y; As[i][k0+6] = v1.z; As[i][k0+7] = v1.w;
        }
        {   // W tile
            int n  = t >> 1;
            int k0 = (t & 1) * 16;
            int gk = kb + k0;
            const float* wp = (K2 == 0 || gk < K1) ? (Wa + (size_t)(n0 + n) * K1 + gk)
                                                   : (Wb + (size_t)(n0 + n) * (K2 ? K2 : 1) + (gk - K1));
#pragma unroll
            for (int j = 0; j < 16; j += 4) {
                float4 w = *(const float4*)(wp + j);
                Ws[k0+j+0][n] = w.x; Ws[k0+j+1][n] = w.y;
                Ws[k0+j+2][n] = w.z; Ws[k0+j+3][n] = w.w;
            }
        }
        __syncthreads();
#pragma unroll
        for (int kk = 0; kk < KCH; ++kk) {
            ulonglong2 wA = ((const ulonglong2*)&Ws[kk][tx * 8])[0];
            ulonglong2 wB = ((const ulonglong2*)&Ws[kk][tx * 8])[1];
#pragma unroll
            for (int i = 0; i < 4; ++i) {
                unsigned au = __float_as_uint(As[ty * 4 + i][kk]);
                unsigned long long ap;
                asm("mov.b64 %0, {%1, %1};" : "=l"(ap) : "r"(au));
                FMA2(acc2[i][0], ap, wA.x);
                FMA2(acc2[i][1], ap, wA.y);
                FMA2(acc2[i][2], ap, wB.x);
                FMA2(acc2[i][3], ap, wB.y);
            }
        }
        __syncthreads();
    }

    float b[8];
#pragma unroll
    for (int j = 0; j < 8; ++j) b[j] = bias[n0 + tx * 8 + j];
#pragma unroll
    for (int i = 0; i < 4; ++i) {
        int ri = ty * 4 + i;
        if (!s_ok[ri]) continue;
        float ov[8];
#pragma unroll
        for (int p2 = 0; p2 < 4; ++p2) {
            unsigned lo, hi;
            asm("mov.b64 {%0, %1}, %2;" : "=r"(lo), "=r"(hi) : "l"(acc2[i][p2]));
            ov[2*p2]   = __uint_as_float(lo) + b[2*p2];
            ov[2*p2+1] = __uint_as_float(hi) + b[2*p2+1];
        }
        if (relu) {
#pragma unroll
            for (int j = 0; j < 8; ++j) ov[j] = fmaxf(ov[j], 0.f);
        }
        float* op = out + (size_t)(row0 + ri) * Nout + n0 + tx * 8;
        ((float4*)op)[0] = make_float4(ov[0], ov[1], ov[2], ov[3]);
        ((float4*)op)[1] = make_float4(ov[4], ov[5], ov[6], ov[7]);
    }
}

struct GJob {
    const int* rowcnt;
    const float* X1; const int* g1;
    const float* X2; const int* g2;
    const float* Wa; const float* Wb; const float* bias;
    float* out;
};

// fused 4-way L1 GEMM: compile-time block-range dispatch
__global__ __launch_bounds__(256) void k_gemm4(GJob j0, GJob j1, GJob j2, GJob j3)
{
    int b = blockIdx.x;
    GJob J; int rb;
    if (b < NBLK_DIS)                    { J = j0; rb = b; }
    else if (b < NBLK_DIS + NBLK_NB)     { J = j1; rb = b - NBLK_DIS; }
    else if (b < NBLK_DIS + 2*NBLK_NB)   { J = j2; rb = b - NBLK_DIS - NBLK_NB; }
    else                                 { J = j3; rb = b - NBLK_DIS - 2*NBLK_NB; }
    int nr = *J.rowcnt;
    if (rb * TMR >= nr) return;
    gemm_body<128,256>(rb, 0, nr, J.X1, J.g1, J.X2, J.g2, J.Wa, J.Wb, J.bias, J.out, 128, 1);
}

// fused 2-way L2 GEMM
__global__ __launch_bounds__(256) void k_gemm2(GJob j0, GJob j1)
{
    int b = blockIdx.x;
    GJob J; int rb;
    if (b < NBLK_NB) { J = j0; rb = b; } else { J = j1; rb = b - NBLK_NB; }
    int nr = *J.rowcnt;
    if (rb * TMR >= nr) return;
    gemm_body<128,256>(rb, 0, nr, J.X1, J.g1, J.X2, J.g2, J.Wa, J.Wb, J.bias, J.out, 128, 1);
}

// generic fixed-rowcount GEMM (pair head)
template<int K1, int K>
__global__ __launch_bounds__(256) void k_gemm(
    int nfixed,
    const float* X1, const int* g1, const float* X2, const int* g2,
    const float* Wa, const float* Wb, const float* bias,
    float* out, int Nout, int relu)
{
    int rb = blockIdx.x;
    if (rb * TMR >= nfixed) return;
    gemm_body<K1,K>(rb, blockIdx.y * 128, nfixed, X1, g1, X2, g2, Wa, Wb, bias, out, Nout, relu);
}

// fold attention (len-1 kv => softmax == 1): A_m = Wout_m @ Wv_m, c_m = Wout_m@bv_m + bout_m
__global__ __launch_bounds__(128) void k_fold1(const float* __restrict__ Win,
                                               const float* __restrict__ bin,
                                               const float* __restrict__ Wout,
                                               const float* __restrict__ bout)
{
    int m = blockIdx.y;
    int tt = blockIdx.x;
    int j = threadIdx.x;
    const float* Wv = Win + (size_t)m * 384 * 128 + 256 * 128;
    const float* Wo = Wout + (size_t)m * 128 * 128;
    const float* bv = bin + m * 384 + 256;
    const float* bo = bout + m * 128;
    const float* worow = Wo + (size_t)tt * 128;
    float s = 0.f;
    for (int u = 0; u < 128; ++u) s += worow[u] * Wv[(size_t)u * 128 + j];
    (m == 0 ? g_A0 : g_A1)[tt * 128 + j] = s;
    __shared__ float red[128];
    red[j] = worow[j] * bv[j];
    __syncthreads();
    for (int o = 64; o > 0; o >>= 1) { if (j < o) red[j] += red[j + o]; __syncthreads(); }
    if (j == 0) (m == 0 ? g_c0 : g_c1)[tt] = red[0] + bo[tt];
}

// fold attention affine maps into mlp_W1: h1 = relu(Md*de + Ms*se + btil)
__global__ __launch_bounds__(128) void k_fold2(const float* __restrict__ W1,
                                               const float* __restrict__ b1)
{
    int o = blockIdx.x, j = threadIdx.x;
    const float* wrow = W1 + (size_t)o * 512;
    float md = wrow[j];
    float ms = wrow[128 + j];
    for (int tt = 0; tt < 128; ++tt) {
        ms += wrow[256 + tt] * g_A0[tt * 128 + j];
        md += wrow[384 + tt] * g_A1[tt * 128 + j];
    }
    g_Md[o * 128 + j] = md;
    g_Ms[o * 128 + j] = ms;
    __shared__ float red[128];
    red[j] = wrow[256 + j] * g_c0[j] + wrow[384 + j] * g_c1[j];
    __syncthreads();
    for (int t2 = 64; t2 > 0; t2 >>= 1) { if (j < t2) red[j] += red[j + t2]; __syncthreads(); }
    if (j == 0) g_btil[o] = red[0] + b1[o];
}

__global__ __launch_bounds__(256) void k_dot(const float* __restrict__ H2,
                                             const float* __restrict__ W3,
                                             const float* __restrict__ b3,
                                             float* __restrict__ out)
{
    int w = (blockIdx.x * blockDim.x + threadIdx.x) >> 5;
    int lane = threadIdx.x & 31;
    if (w >= NB) return;
    float4 h = ((const float4*)(H2 + (size_t)w * 128))[lane];
    float4 c = ((const float4*)W3)[lane];
    float s = h.x * c.x + h.y * c.y + h.z * c.z + h.w * c.w;
    for (int o = 16; o; o >>= 1) s += __shfl_xor_sync(0xffffffffu, s, o);
    if (lane == 0) out[w] = s + b3[0];
}

// ---------------- host ----------------
static inline int ceildiv(int a, int b) { return (a + b - 1) / b; }

extern "C" void kernel_launch(void* const* d_in, const int* in_sizes, int n_in,
                              void* d_out, int out_size)
{
    int fi, ii;
    if (in_sizes[0] == NE) { ii = 0; fi = 6; } else { fi = 0; ii = 15; }
    const float* emb_drug  = (const float*)d_in[fi + 0];
    const float* emb_dis   = (const float*)d_in[fi + 1];
    const float* conv_Wl   = (const float*)d_in[fi + 2];
    const float* conv_bl   = (const float*)d_in[fi + 3];
    const float* conv_Wr   = (const float*)d_in[fi + 4];
    const float* attn_Win  = (const float*)d_in[fi + 5];
    const float* attn_bin  = (const float*)d_in[fi + 6];
    const float* attn_Wout = (const float*)d_in[fi + 7];
    const float* attn_bout = (const float*)d_in[fi + 8];
    const float* mlp_W1    = (const float*)d_in[fi + 9];
    const float* mlp_b1    = (const float*)d_in[fi + 10];
    const float* mlp_W2    = (const float*)d_in[fi + 11];
    const float* mlp_b2    = (const float*)d_in[fi + 12];
    const float* mlp_W3    = (const float*)d_in[fi + 13];
    const float* mlp_b3    = (const float*)d_in[fi + 14];
    const int* src_d2di    = (const int*)d_in[ii + 0];
    const int* dst_d2di    = (const int*)d_in[ii + 1];
    const int* src_di2dr   = (const int*)d_in[ii + 2];
    const int* dst_di2dr   = (const int*)d_in[ii + 3];
    const int* drug_idx    = (const int*)d_in[ii + 4];
    const int* disease_idx = (const int*)d_in[ii + 5];
    float* out = (float*)d_out;

    void* p;
    cudaGetSymbolAddress(&p, g_aggc_dis);   float* aggc_dis   = (float*)p;
    cudaGetSymbolAddress(&p, g_aggc_drug);  float* aggc_drug  = (float*)p;
    cudaGetSymbolAddress(&p, g_head_dis);   int*   head_dis   = (int*)p;
    cudaGetSymbolAddress(&p, g_head_drug);  int*   head_drug  = (int*)p;
    cudaGetSymbolAddress(&p, g_next_dis);   int*   next_dis   = (int*)p;
    cudaGetSymbolAddress(&p, g_next_drug);  int*   next_drug  = (int*)p;
    cudaGetSymbolAddress(&p, g_dis_L1_0);   float* dis_L1_0   = (float*)p;
    cudaGetSymbolAddress(&p, g_dis_L1_1);   float* dis_L1_1   = (float*)p;
    cudaGetSymbolAddress(&p, g_drug_L1_0);  float* drug_L1_0  = (float*)p;
    cudaGetSymbolAddress(&p, g_drug_L1_1);  float* drug_L1_1  = (float*)p;
    cudaGetSymbolAddress(&p, g_drug_L2);    float* drug_L2    = (float*)p;
    cudaGetSymbolAddress(&p, g_dis_L2);     float* dis_L2     = (float*)p;
    cudaGetSymbolAddress(&p, g_l_dis_s0);   int* l_dis_s0     = (int*)p;
    cudaGetSymbolAddress(&p, g_l_dis_s1);   int* l_dis_s1     = (int*)p;
    cudaGetSymbolAddress(&p, g_l_dis_ag);   int* l_dis_ag     = (int*)p;
    cudaGetSymbolAddress(&p, g_l_drug_s0);  int* l_drug_s0    = (int*)p;
    cudaGetSymbolAddress(&p, g_l_drug_s1);  int* l_drug_s1    = (int*)p;
    cudaGetSymbolAddress(&p, g_l_drug_ag);  int* l_drug_ag    = (int*)p;
    cudaGetSymbolAddress(&p, g_s_dis_s0);   int* s_dis_s0     = (int*)p;
    cudaGetSymbolAddress(&p, g_s_drug_s1);  int* s_drug_s1    = (int*)p;
    cudaGetSymbolAddress(&p, g_a1_dis_s0);  int* a1_dis_s0    = (int*)p;
    cudaGetSymbolAddress(&p, g_a1_dis_s1);  int* a1_dis_s1    = (int*)p;
    cudaGetSymbolAddress(&p, g_a1_drug_s0); int* a1_drug_s0   = (int*)p;
    cudaGetSymbolAddress(&p, g_a1_drug_s1); int* a1_drug_s1   = (int*)p;
    cudaGetSymbolAddress(&p, g_gd);         int* gd           = (int*)p;
    cudaGetSymbolAddress(&p, g_gs);         int* gs           = (int*)p;
    cudaGetSymbolAddress(&p, g_ctr);        int* ctr          = (int*)p;
    cudaGetSymbolAddress(&p, g_Md);         float* Md         = (float*)p;
    cudaGetSymbolAddress(&p, g_Ms);         float* Ms         = (float*)p;
    cudaGetSymbolAddress(&p, g_btil);       float* btil       = (float*)p;
    cudaGetSymbolAddress(&p, g_H1);         float* H1         = (float*)p;
    cudaGetSymbolAddress(&p, g_H2);         float* H2         = (float*)p;

    auto woff = [](int s, int l, int et) { return (size_t)((s * 2 + l) * 2 + et) * 128 * 128; };
    auto boff = [](int s, int l, int et) { return (size_t)((s * 2 + l) * 2 + et) * 128; };

    // 1. init + mark + fused link/frontier
    k_init<<<ceildiv(N_DRUG, 256), 256>>>();
    k_mark<<<ceildiv(NB, 256), 256>>>(drug_idx, disease_idx);
    k_link<<<ceildiv(2 * NE, 256), 256>>>(src_d2di, dst_d2di, src_di2dr, dst_di2dr);
    // 2. L1 gather-mean, both sides in one launch
    k_gather2<<<dim3(ceildiv(N_DRUG * 32, 256), 2), 256>>>(
        l_dis_ag, ctr + C_DIS_AG, head_dis, next_dis, src_d2di, nullptr, emb_drug, aggc_dis,
        l_drug_ag, ctr + C_DRUG_AG, head_drug, next_drug, src_di2dr, nullptr, emb_dis, aggc_drug);
    // 3. per-row gather index composition
    k_compose<<<dim3(ceildiv(N_DRUG, 256), 6), 256>>>(drug_idx, disease_idx);
    // 4. fused L1 GEMMs (4 jobs, one launch)
    GJob jd0 = { ctr + C_DIS_S0,  aggc_dis,  a1_dis_s0,  emb_dis,  l_dis_s0,
                 conv_Wl + woff(0,0,0), conv_Wr + woff(0,0,0), conv_bl + boff(0,0,0), dis_L1_0 };
    GJob jd1 = { ctr + C_DIS_S1,  aggc_dis,  a1_dis_s1,  emb_dis,  l_dis_s1,
                 conv_Wl + woff(1,0,0), conv_Wr + woff(1,0,0), conv_bl + boff(1,0,0), dis_L1_1 };
    GJob jr0 = { ctr + C_DRUG_S0, aggc_drug, a1_drug_s0, emb_drug, l_drug_s0,
                 conv_Wl + woff(0,0,1), conv_Wr + woff(0,0,1), conv_bl + boff(0,0,1), drug_L1_0 };
    GJob jr1 = { ctr + C_DRUG_S1, aggc_drug, a1_drug_s1, emb_drug, l_drug_s1,
                 conv_Wl + woff(1,0,1), conv_Wr + woff(1,0,1), conv_bl + boff(1,0,1), drug_L1_1 };
    k_gemm4<<<NBLK_L1, 256>>>(jd0, jd1, jr0, jr1);
    // 5. L2 gather-mean, both sides in one launch
    k_gather2<<<dim3(ceildiv(NB * 32, 256), 2), 256>>>(
        l_drug_s0, ctr + C_DRUG_S0, head_drug, next_drug, src_di2dr, s_dis_s0, dis_L1_0, aggc_drug,
        l_dis_s1, ctr + C_DIS_S1, head_dis, next_dis, src_d2di, s_drug_s1, drug_L1_1, aggc_dis);
    // 6. fused L2 GEMMs (2 jobs, one launch)
    GJob jl0 = { ctr + C_DRUG_S0, aggc_drug, nullptr, drug_L1_0, nullptr,
                 conv_Wl + woff(0,1,1), conv_Wr + woff(0,1,1), conv_bl + boff(0,1,1), drug_L2 };
    GJob jl1 = { ctr + C_DIS_S1,  aggc_dis,  nullptr, dis_L1_1,  nullptr,
                 conv_Wl + woff(1,1,0), conv_Wr + woff(1,1,0), conv_bl + boff(1,1,0), dis_L2 };
    k_gemm2<<<2 * NBLK_NB, 256>>>(jl0, jl1);
    // 7. fold degenerate MHA into MLP layer 1
    k_fold1<<<dim3(128, 2), 128>>>(attn_Win, attn_bin, attn_Wout, attn_bout);
    k_fold2<<<256, 128>>>(mlp_W1, mlp_b1);
    // 8. pair head
    k_gemm<128,256><<<dim3(NBLK_NB, 2), 256>>>(NB, drug_L2, gd, dis_L2, gs,
                                               Md, Ms, btil, H1, 256, 1);
    k_gemm<256,256><<<dim3(NBLK_NB, 1), 256>>>(NB, H1, nullptr, H1, nullptr,
                                               mlp_W2, mlp_W2, mlp_b2, H2, 128, 1);
    k_dot<<<ceildiv(NB * 32, 256), 256>>>(H2, mlp_W3, mlp_b3, out);
}

// round 16
// speedup vs baseline: 2.7715x; 1.6409x over previous
#include <cuda_runtime.h>
#include <cuda_bf16.h>
#include <cstdint>

#define N_DRUG 200000
#define N_DIS  100000
#define HDIM   128
#define NE     600000
#define NB     8192

#define C_DIS_S0  0
#define C_DIS_S1  1
#define C_DIS_AG  2
#define C_DRUG_S0 3
#define C_DRUG_S1 4
#define C_DRUG_AG 5

#define TMR 64
#define KCH 32
#define NBLK_DIS  ((N_DIS  + TMR - 1) / TMR)
#define NBLK_NB   ((NB     + TMR - 1) / TMR)
#define NBLK_DRUG ((N_DRUG + TMR - 1) / TMR)
#define NBLK_L1   (NBLK_DIS + 2 * NBLK_NB + NBLK_DRUG)

#define BM_DIS  ((N_DIS  + 31) / 32)
#define BM_DRUG ((N_DRUG + 31) / 32)

// ---------------- device scratch ----------------
__device__ float g_aggc_dis [(size_t)N_DIS  * HDIM];
__device__ float g_aggc_drug[(size_t)N_DRUG * HDIM];
__device__ int   g_head_dis [N_DIS];
__device__ int   g_head_drug[N_DRUG];
__device__ int   g_next_dis [NE];
__device__ int   g_next_drug[NE];
__device__ float g_dis_L1_0 [(size_t)N_DIS  * HDIM];
__device__ float g_dis_L1_1 [(size_t)NB     * HDIM];
__device__ float g_drug_L1_0[(size_t)NB     * HDIM];
__device__ float g_drug_L1_1[(size_t)N_DRUG * HDIM];
__device__ float g_drug_L2 [(size_t)NB * HDIM];
__device__ float g_dis_L2  [(size_t)NB * HDIM];
__device__ int g_m_dis_s0[N_DIS],  g_m_dis_s1[N_DIS],  g_m_dis_ag[N_DIS];
__device__ int g_m_drug_s0[N_DRUG],g_m_drug_s1[N_DRUG],g_m_drug_ag[N_DRUG];
__device__ unsigned g_bm_dis_s1[BM_DIS];     // hot read masks for k_link (L2-resident)
__device__ unsigned g_bm_drug_s0[BM_DRUG];
__device__ int g_l_dis_s0[N_DIS],  g_l_dis_s1[N_DIS],  g_l_dis_ag[N_DIS];
__device__ int g_l_drug_s0[N_DRUG],g_l_drug_s1[N_DRUG],g_l_drug_ag[N_DRUG];
__device__ int g_s_dis_s0[N_DIS],  g_s_dis_s1[N_DIS],  g_s_dis_ag[N_DIS];
__device__ int g_s_drug_s0[N_DRUG],g_s_drug_s1[N_DRUG],g_s_drug_ag[N_DRUG];
__device__ int g_a1_dis_s0[N_DIS], g_a1_dis_s1[NB], g_a1_drug_s0[NB], g_a1_drug_s1[N_DRUG];
__device__ int g_gd[NB], g_gs[NB];
__device__ int g_ctr[8];
__device__ float g_A0[HDIM*HDIM], g_A1[HDIM*HDIM], g_c0[HDIM], g_c1[HDIM];
__device__ float g_Md[256*HDIM], g_Ms[256*HDIM], g_btil[256];
__device__ float g_H1[(size_t)NB * 256];
__device__ float g_H2[(size_t)NB * HDIM];

// ---------------- init ----------------
__global__ __launch_bounds__(256) void k_init()
{
    int i = blockIdx.x * blockDim.x + threadIdx.x;
    if (i < N_DIS) {
        g_m_dis_s0[i] = 0; g_m_dis_s1[i] = 0; g_m_dis_ag[i] = 0; g_head_dis[i] = -1;
    }
    if (i < N_DRUG) {
        g_m_drug_s0[i] = 0; g_m_drug_s1[i] = 0; g_m_drug_ag[i] = 0; g_head_drug[i] = -1;
    }
    if (i < BM_DIS)  g_bm_dis_s1[i]  = 0u;
    if (i < BM_DRUG) g_bm_drug_s0[i] = 0u;
    if (i < 8) g_ctr[i] = 0;
}

// mark targets; record compact slots at claim time; set hot bitmasks
__global__ __launch_bounds__(256) void k_mark(const int* __restrict__ drug_idx,
                                              const int* __restrict__ disease_idx)
{
    int i = blockIdx.x * blockDim.x + threadIdx.x;
    if (i >= NB) return;
    int d = drug_idx[i];
    if (atomicExch(&g_m_drug_s0[d], 1) == 0) {
        int p = atomicAdd(&g_ctr[C_DRUG_S0], 1); g_l_drug_s0[p] = d; g_s_drug_s0[d] = p;
        atomicOr(&g_bm_drug_s0[d >> 5], 1u << (d & 31));
    }
    if (atomicExch(&g_m_drug_ag[d], 1) == 0) {
        int p = atomicAdd(&g_ctr[C_DRUG_AG], 1); g_l_drug_ag[p] = d; g_s_drug_ag[d] = p;
    }
    int s = disease_idx[i];
    if (atomicExch(&g_m_dis_s1[s], 1) == 0) {
        int p = atomicAdd(&g_ctr[C_DIS_S1], 1); g_l_dis_s1[p] = s; g_s_dis_s1[s] = p;
        atomicOr(&g_bm_dis_s1[s >> 5], 1u << (s & 31));
    }
    if (atomicExch(&g_m_dis_ag[s], 1) == 0) {
        int p = atomicAdd(&g_ctr[C_DIS_AG], 1); g_l_dis_ag[p] = s; g_s_dis_ag[s] = p;
    }
}

// fused: one-pass linked-list CSR + frontier marking (bitmask hot path)
__global__ __launch_bounds__(256) void k_link(const int* __restrict__ src_d2di,
                                              const int* __restrict__ dst_d2di,
                                              const int* __restrict__ src_di2dr,
                                              const int* __restrict__ dst_di2dr)
{
    int e = blockIdx.x * blockDim.x + threadIdx.x;
    if (e < NE) {
        int d = dst_d2di[e];
        g_next_dis[e] = atomicExch(&g_head_dis[d], e);
        if ((__ldg(&g_bm_dis_s1[d >> 5]) >> (d & 31)) & 1u) {
            int s = __ldg(src_d2di + e);
            if (atomicExch(&g_m_drug_s1[s], 1) == 0) {
                int p = atomicAdd(&g_ctr[C_DRUG_S1], 1); g_l_drug_s1[p] = s; g_s_drug_s1[s] = p;
            }
            if (atomicExch(&g_m_drug_ag[s], 1) == 0) {
                int p = atomicAdd(&g_ctr[C_DRUG_AG], 1); g_l_drug_ag[p] = s; g_s_drug_ag[s] = p;
            }
        }
    } else if (e < 2 * NE) {
        int e2 = e - NE;
        int d = dst_di2dr[e2];
        g_next_drug[e2] = atomicExch(&g_head_drug[d], e2);
        if ((__ldg(&g_bm_drug_s0[d >> 5]) >> (d & 31)) & 1u) {
            int s = __ldg(src_di2dr + e2);
            if (atomicExch(&g_m_dis_s0[s], 1) == 0) {
                int p = atomicAdd(&g_ctr[C_DIS_S0], 1); g_l_dis_s0[p] = s; g_s_dis_s0[s] = p;
            }
            if (atomicExch(&g_m_dis_ag[s], 1) == 0) {
                int p = atomicAdd(&g_ctr[C_DIS_AG], 1); g_l_dis_ag[p] = s; g_s_dis_ag[s] = p;
            }
        }
    }
}

// warp-per-node chain-walk gather-mean body
__device__ __forceinline__ void gather_body(int w, int lane,
                                            const int* __restrict__ list,
                                            const int* __restrict__ cntp,
                                            const int* __restrict__ head,
                                            const int* __restrict__ next,
                                            const int* __restrict__ srcArr,
                                            const int* __restrict__ slotmap,
                                            const float* __restrict__ X,
                                            float* __restrict__ out)
{
    if (w >= *cntp) return;
    int node = list[w];
    float4 acc = make_float4(0.f, 0.f, 0.f, 0.f);
    int n = 0;
    int e = head[node];
    while (e >= 0) {
        int nx = __ldg(next + e);
        int s = __ldg(srcArr + e);
        int row = slotmap ? slotmap[s] : s;
        float4 v = ((const float4*)(X + (size_t)row * HDIM))[lane];
        acc.x += v.x; acc.y += v.y; acc.z += v.z; acc.w += v.w;
        ++n;
        e = nx;
    }
    float inv = n ? 1.f / (float)n : 0.f;
    acc.x *= inv; acc.y *= inv; acc.z *= inv; acc.w *= inv;
    ((float4*)(out + (size_t)w * HDIM))[lane] = acc;
}

__global__ __launch_bounds__(256) void k_gather2(
    const int* l0, const int* c0, const int* h0, const int* n0p, const int* s0, const int* sm0, const float* X0, float* o0,
    const int* l1, const int* c1, const int* h1, const int* n1p, const int* s1, const int* sm1, const float* X1, float* o1)
{
    int w = (blockIdx.x * blockDim.x + threadIdx.x) >> 5;
    int lane = threadIdx.x & 31;
    if (blockIdx.y == 0)
        gather_body(w, lane, l0, c0, h0, n0p, s0, sm0, X0, o0);
    else
        gather_body(w, lane, l1, c1, h1, n1p, s1, sm1, X1, o1);
}

// compose per-row gather indices (6 segments via blockIdx.y)
__global__ __launch_bounds__(256) void k_compose(const int* __restrict__ drug_idx,
                                                 const int* __restrict__ disease_idx)
{
    int y = blockIdx.y;
    int i = blockIdx.x * blockDim.x + threadIdx.x;
    switch (y) {
    case 0: if (i < g_ctr[C_DIS_S0])  g_a1_dis_s0[i]  = g_s_dis_ag[g_l_dis_s0[i]];   break;
    case 1: if (i < g_ctr[C_DIS_S1])  g_a1_dis_s1[i]  = g_s_dis_ag[g_l_dis_s1[i]];   break;
    case 2: if (i < g_ctr[C_DRUG_S0]) g_a1_drug_s0[i] = g_s_drug_ag[g_l_drug_s0[i]]; break;
    case 3: if (i < g_ctr[C_DRUG_S1]) g_a1_drug_s1[i] = g_s_drug_ag[g_l_drug_s1[i]]; break;
    case 4: if (i < NB)               g_gd[i]         = g_s_drug_s0[drug_idx[i]];    break;
    case 5: if (i < NB)               g_gs[i]         = g_s_dis_s1[disease_idx[i]];  break;
    }
}

// ---------------- tiled GEMM via tf32 mma.sync (HMMA tensor cores) ----------------
// 64x128 tile, K chunks of 32. 8 warps: rg = wid&3 (16 rows), cg = wid>>2 (64 cols).
// Pads: As stride 36 (36%32==4 -> 4r+c bijective on banks), Ws stride 136 (8k+n bijective).
#define CVT_TF32(d, f) asm("cvt.rna.tf32.f32 %0, %1;" : "=r"(d) : "f"(f))

template<int K1, int K>
__device__ __forceinline__ void gemm_body(
    int rb, int n0, int nr,
    const float* __restrict__ X1, const int* __restrict__ g1,
    const float* __restrict__ X2, const int* __restrict__ g2,
    const float* __restrict__ Wa, const float* __restrict__ Wb,
    const float* __restrict__ bias,
    float* __restrict__ out, int Nout, int relu)
{
    __shared__ float As[TMR][36];
    __shared__ float Ws[KCH][136];
    __shared__ int   s_a1[TMR], s_a2[TMR], s_ok[TMR];

    int row0 = rb * TMR;
    int t = threadIdx.x;

    if (t < TMR) {
        int r = row0 + t;
        int ok = r < nr;
        s_a1[t] = ok ? (g1 ? g1[r] : r) : 0;
        s_a2[t] = ok ? (g2 ? g2[r] : r) : 0;
        s_ok[t] = ok;
    }
    __syncthreads();

    int wid  = t >> 5;
    int lane = t & 31;
    int rg = wid & 3;            // row group (x16)
    int cg = wid >> 2;           // col group (x64)
    int fr = lane >> 2;          // 0..7
    int fc = lane & 3;           // 0..3

    float dacc[8][4];
#pragma unroll
    for (int nt = 0; nt < 8; ++nt)
#pragma unroll
        for (int j = 0; j < 4; ++j) dacc[nt][j] = 0.f;

    constexpr int K2 = K - K1;
    constexpr int NCH = K / KCH;

#pragma unroll
    for (int c = 0; c < NCH; ++c) {
        int kb = c * KCH;
        {   // A tile
            int i  = t >> 2;
            int k0 = (t & 3) * 8;
            float4 v0 = make_float4(0.f, 0.f, 0.f, 0.f), v1 = v0;
            if (s_ok[i]) {
                int k = kb + k0;
                if (K2 == 0 || k < K1) {
                    const float4* p = (const float4*)(X1 + (size_t)s_a1[i] * K1 + k);
                    v0 = p[0]; v1 = p[1];
                } else {
                    const float4* p = (const float4*)(X2 + (size_t)s_a2[i] * (K2 ? K2 : 1) + (k - K1));
                    v0 = p[0]; v1 = p[1];
                }
            }
            As[i][k0+0] = v0.x; As[i][k0+1] = v0.y; As[i][k0+2] = v0.z; As[i][k0+3] = v0.w;
            As[i][k0+4] = v1.x; As[i][k0+5] = v1.y; As[i][k0+6] = v1.z; As[i][k0+7] = v1.w;
        }
        {   // W tile
            int n  = t >> 1;
            int k0 = (t & 1) * 16;
            int gk = kb + k0;
            const float* wp = (K2 == 0 || gk < K1) ? (Wa + (size_t)(n0 + n) * K1 + gk)
                                                   : (Wb + (size_t)(n0 + n) * (K2 ? K2 : 1) + (gk - K1));
#pragma unroll
            for (int j = 0; j < 16; j += 4) {
                float4 w = *(const float4*)(wp + j);
                Ws[k0+j+0][n] = w.x; Ws[k0+j+1][n] = w.y;
                Ws[k0+j+2][n] = w.z; Ws[k0+j+3][n] = w.w;
            }
        }
        __syncthreads();
#pragma unroll
        for (int ks = 0; ks < KCH / 8; ++ks) {
            int kb2 = ks * 8;
            uint32_t a0, a1, a2, a3;
            CVT_TF32(a0, As[rg*16 + fr    ][kb2 + fc    ]);
            CVT_TF32(a1, As[rg*16 + fr + 8][kb2 + fc    ]);
            CVT_TF32(a2, As[rg*16 + fr    ][kb2 + fc + 4]);
            CVT_TF32(a3, As[rg*16 + fr + 8][kb2 + fc + 4]);
#pragma unroll
            for (int nt = 0; nt < 8; ++nt) {
                int ncol = cg * 64 + nt * 8 + fr;
                uint32_t b0, b1;
                CVT_TF32(b0, Ws[kb2 + fc    ][ncol]);
                CVT_TF32(b1, Ws[kb2 + fc + 4][ncol]);
                asm volatile(
                    "mma.sync.aligned.m16n8k8.row.col.f32.tf32.tf32.f32 "
                    "{%0,%1,%2,%3}, {%4,%5,%6,%7}, {%8,%9}, {%0,%1,%2,%3};"
                    : "+f"(dacc[nt][0]), "+f"(dacc[nt][1]),
                      "+f"(dacc[nt][2]), "+f"(dacc[nt][3])
                    : "r"(a0), "r"(a1), "r"(a2), "r"(a3), "r"(b0), "r"(b1));
            }
        }
        __syncthreads();
    }

    int okA = s_ok[rg*16 + fr];
    int okB = s_ok[rg*16 + fr + 8];
    size_t rowA = (size_t)(row0 + rg*16 + fr) * Nout;
    size_t rowB = rowA + (size_t)8 * Nout;
#pragma unroll
    for (int nt = 0; nt < 8; ++nt) {
        int col = n0 + cg * 64 + nt * 8 + 2 * fc;
        float bv0 = __ldg(bias + col), bv1 = __ldg(bias + col + 1);
        if (okA) {
            float o0 = dacc[nt][0] + bv0, o1 = dacc[nt][1] + bv1;
            if (relu) { o0 = fmaxf(o0, 0.f); o1 = fmaxf(o1, 0.f); }
            *(float2*)(out + rowA + col) = make_float2(o0, o1);
        }
        if (okB) {
            float o2 = dacc[nt][2] + bv0, o3 = dacc[nt][3] + bv1;
            if (relu) { o2 = fmaxf(o2, 0.f); o3 = fmaxf(o3, 0.f); }
            *(float2*)(out + rowB + col) = make_float2(o2, o3);
        }
    }
}

struct GJob {
    const int* rowcnt;
    const float* X1; const int* g1;
    const float* X2; const int* g2;
    const float* Wa; const float* Wb; const float* bias;
    float* out;
};

__global__ __launch_bounds__(256) void k_gemm4(GJob j0, GJob j1, GJob j2, GJob j3)
{
    int b = blockIdx.x;
    GJob J; int rb;
    if (b < NBLK_DIS)                    { J = j0; rb = b; }
    else if (b < NBLK_DIS + NBLK_NB)     { J = j1; rb = b - NBLK_DIS; }
    else if (b < NBLK_DIS + 2*NBLK_NB)   { J = j2; rb = b - NBLK_DIS - NBLK_NB; }
    else                                 { J = j3; rb = b - NBLK_DIS - 2*NBLK_NB; }
    int nr = *J.rowcnt;
    if (rb * TMR >= nr) return;
    gemm_body<128,256>(rb, 0, nr, J.X1, J.g1, J.X2, J.g2, J.Wa, J.Wb, J.bias, J.out, 128, 1);
}

__global__ __launch_bounds__(256) void k_gemm2(GJob j0, GJob j1)
{
    int b = blockIdx.x;
    GJob J; int rb;
    if (b < NBLK_NB) { J = j0; rb = b; } else { J = j1; rb = b - NBLK_NB; }
    int nr = *J.rowcnt;
    if (rb * TMR >= nr) return;
    gemm_body<128,256>(rb, 0, nr, J.X1, J.g1, J.X2, J.g2, J.Wa, J.Wb, J.bias, J.out, 128, 1);
}

template<int K1, int K>
__global__ __launch_bounds__(256) void k_gemm(
    int nfixed,
    const float* X1, const int* g1, const float* X2, const int* g2,
    const float* Wa, const float* Wb, const float* bias,
    float* out, int Nout, int relu)
{
    int rb = blockIdx.x;
    if (rb * TMR >= nfixed) return;
    gemm_body<K1,K>(rb, blockIdx.y * 128, nfixed, X1, g1, X2, g2, Wa, Wb, bias, out, Nout, relu);
}

// fold attention (len-1 kv => softmax == 1)
__global__ __launch_bounds__(128) void k_fold1(const float* __restrict__ Win,
                                               const float* __restrict__ bin,
                                               const float* __restrict__ Wout,
                                               const float* __restrict__ bout)
{
    int m = blockIdx.y;
    int tt = blockIdx.x;
    int j = threadIdx.x;
    const float* Wv = Win + (size_t)m * 384 * 128 + 256 * 128;
    const float* Wo = Wout + (size_t)m * 128 * 128;
    const float* bv = bin + m * 384 + 256;
    const float* bo = bout + m * 128;
    const float* worow = Wo + (size_t)tt * 128;
    float s = 0.f;
    for (int u = 0; u < 128; ++u) s += worow[u] * Wv[(size_t)u * 128 + j];
    (m == 0 ? g_A0 : g_A1)[tt * 128 + j] = s;
    __shared__ float red[128];
    red[j] = worow[j] * bv[j];
    __syncthreads();
    for (int o = 64; o > 0; o >>= 1) { if (j < o) red[j] += red[j + o]; __syncthreads(); }
    if (j == 0) (m == 0 ? g_c0 : g_c1)[tt] = red[0] + bo[tt];
}

__global__ __launch_bounds__(128) void k_fold2(const float* __restrict__ W1,
                                               const float* __restrict__ b1)
{
    int o = blockIdx.x, j = threadIdx.x;
    const float* wrow = W1 + (size_t)o * 512;
    float md = wrow[j];
    float ms = wrow[128 + j];
    for (int tt = 0; tt < 128; ++tt) {
        ms += wrow[256 + tt] * g_A0[tt * 128 + j];
        md += wrow[384 + tt] * g_A1[tt * 128 + j];
    }
    g_Md[o * 128 + j] = md;
    g_Ms[o * 128 + j] = ms;
    __shared__ float red[128];
    red[j] = wrow[256 + j] * g_c0[j] + wrow[384 + j] * g_c1[j];
    __syncthreads();
    for (int t2 = 64; t2 > 0; t2 >>= 1) { if (j < t2) red[j] += red[j + t2]; __syncthreads(); }
    if (j == 0) g_btil[o] = red[0] + b1[o];
}

__global__ __launch_bounds__(256) void k_dot(const float* __restrict__ H2,
                                             const float* __restrict__ W3,
                                             const float* __restrict__ b3,
                                             float* __restrict__ out)
{
    int w = (blockIdx.x * blockDim.x + threadIdx.x) >> 5;
    int lane = threadIdx.x & 31;
    if (w >= NB) return;
    float4 h = ((const float4*)(H2 + (size_t)w * 128))[lane];
    float4 c = ((const float4*)W3)[lane];
    float s = h.x * c.x + h.y * c.y + h.z * c.z + h.w * c.w;
    for (int o = 16; o; o >>= 1) s += __shfl_xor_sync(0xffffffffu, s, o);
    if (lane == 0) out[w] = s + b3[0];
}

// ---------------- host ----------------
static inline int ceildiv(int a, int b) { return (a + b - 1) / b; }

extern "C" void kernel_launch(void* const* d_in, const int* in_sizes, int n_in,
                              void* d_out, int out_size)
{
    int fi, ii;
    if (in_sizes[0] == NE) { ii = 0; fi = 6; } else { fi = 0; ii = 15; }
    const float* emb_drug  = (const float*)d_in[fi + 0];
    const float* emb_dis   = (const float*)d_in[fi + 1];
    const float* conv_Wl   = (const float*)d_in[fi + 2];
    const float* conv_bl   = (const float*)d_in[fi + 3];
    const float* conv_Wr   = (const float*)d_in[fi + 4];
    const float* attn_Win  = (const float*)d_in[fi + 5];
    const float* attn_bin  = (const float*)d_in[fi + 6];
    const float* attn_Wout = (const float*)d_in[fi + 7];
    const float* attn_bout = (const float*)d_in[fi + 8];
    const float* mlp_W1    = (const float*)d_in[fi + 9];
    const float* mlp_b1    = (const float*)d_in[fi + 10];
    const float* mlp_W2    = (const float*)d_in[fi + 11];
    const float* mlp_b2    = (const float*)d_in[fi + 12];
    const float* mlp_W3    = (const float*)d_in[fi + 13];
    const float* mlp_b3    = (const float*)d_in[fi + 14];
    const int* src_d2di    = (const int*)d_in[ii + 0];
    const int* dst_d2di    = (const int*)d_in[ii + 1];
    const int* src_di2dr   = (const int*)d_in[ii + 2];
    const int* dst_di2dr   = (const int*)d_in[ii + 3];
    const int* drug_idx    = (const int*)d_in[ii + 4];
    const int* disease_idx = (const int*)d_in[ii + 5];
    float* out = (float*)d_out;

    void* p;
    cudaGetSymbolAddress(&p, g_aggc_dis);   float* aggc_dis   = (float*)p;
    cudaGetSymbolAddress(&p, g_aggc_drug);  float* aggc_drug  = (float*)p;
    cudaGetSymbolAddress(&p, g_head_dis);   int*   head_dis   = (int*)p;
    cudaGetSymbolAddress(&p, g_head_drug);  int*   head_drug  = (int*)p;
    cudaGetSymbolAddress(&p, g_next_dis);   int*   next_dis   = (int*)p;
    cudaGetSymbolAddress(&p, g_next_drug);  int*   next_drug  = (int*)p;
    cudaGetSymbolAddress(&p, g_dis_L1_0);   float* dis_L1_0   = (float*)p;
    cudaGetSymbolAddress(&p, g_dis_L1_1);   float* dis_L1_1   = (float*)p;
    cudaGetSymbolAddress(&p, g_drug_L1_0);  float* drug_L1_0  = (float*)p;
    cudaGetSymbolAddress(&p, g_drug_L1_1);  float* drug_L1_1  = (float*)p;
    cudaGetSymbolAddress(&p, g_drug_L2);    float* drug_L2    = (float*)p;
    cudaGetSymbolAddress(&p, g_dis_L2);     float* dis_L2     = (float*)p;
    cudaGetSymbolAddress(&p, g_l_dis_s0);   int* l_dis_s0     = (int*)p;
    cudaGetSymbolAddress(&p, g_l_dis_s1);   int* l_dis_s1     = (int*)p;
    cudaGetSymbolAddress(&p, g_l_dis_ag);   int* l_dis_ag     = (int*)p;
    cudaGetSymbolAddress(&p, g_l_drug_s0);  int* l_drug_s0    = (int*)p;
    cudaGetSymbolAddress(&p, g_l_drug_s1);  int* l_drug_s1    = (int*)p;
    cudaGetSymbolAddress(&p, g_l_drug_ag);  int* l_drug_ag    = (int*)p;
    cudaGetSymbolAddress(&p, g_s_dis_s0);   int* s_dis_s0     = (int*)p;
    cudaGetSymbolAddress(&p, g_s_drug_s1);  int* s_drug_s1    = (int*)p;
    cudaGetSymbolAddress(&p, g_a1_dis_s0);  int* a1_dis_s0    = (int*)p;
    cudaGetSymbolAddress(&p, g_a1_dis_s1);  int* a1_dis_s1    = (int*)p;
    cudaGetSymbolAddress(&p, g_a1_drug_s0); int* a1_drug_s0   = (int*)p;
    cudaGetSymbolAddress(&p, g_a1_drug_s1); int* a1_drug_s1   = (int*)p;
    cudaGetSymbolAddress(&p, g_gd);         int* gd           = (int*)p;
    cudaGetSymbolAddress(&p, g_gs);         int* gs           = (int*)p;
    cudaGetSymbolAddress(&p, g_ctr);        int* ctr          = (int*)p;
    cudaGetSymbolAddress(&p, g_Md);         float* Md         = (float*)p;
    cudaGetSymbolAddress(&p, g_Ms);         float* Ms         = (float*)p;
    cudaGetSymbolAddress(&p, g_btil);       float* btil       = (float*)p;
    cudaGetSymbolAddress(&p, g_H1);         float* H1         = (float*)p;
    cudaGetSymbolAddress(&p, g_H2);         float* H2         = (float*)p;

    auto woff = [](int s, int l, int et) { return (size_t)((s * 2 + l) * 2 + et) * 128 * 128; };
    auto boff = [](int s, int l, int et) { return (size_t)((s * 2 + l) * 2 + et) * 128; };

    // 1. init + mark + fused link/frontier
    k_init<<<ceildiv(N_DRUG, 256), 256>>>();
    k_mark<<<ceildiv(NB, 256), 256>>>(drug_idx, disease_idx);
    k_link<<<ceildiv(2 * NE, 256), 256>>>(src_d2di, dst_d2di, src_di2dr, dst_di2dr);
    // 2. L1 gather-mean, both sides in one launch
    k_gather2<<<dim3(ceildiv(N_DRUG * 32, 256), 2), 256>>>(
        l_dis_ag, ctr + C_DIS_AG, head_dis, next_dis, src_d2di, nullptr, emb_drug, aggc_dis,
        l_drug_ag, ctr + C_DRUG_AG, head_drug, next_drug, src_di2dr, nullptr, emb_dis, aggc_drug);
    // 3. per-row gather index composition
    k_compose<<<dim3(ceildiv(N_DRUG, 256), 6), 256>>>(drug_idx, disease_idx);
    // 4. fused L1 GEMMs (tf32 tensor cores)
    GJob jd0 = { ctr + C_DIS_S0,  aggc_dis,  a1_dis_s0,  emb_dis,  l_dis_s0,
                 conv_Wl + woff(0,0,0), conv_Wr + woff(0,0,0), conv_bl + boff(0,0,0), dis_L1_0 };
    GJob jd1 = { ctr + C_DIS_S1,  aggc_dis,  a1_dis_s1,  emb_dis,  l_dis_s1,
                 conv_Wl + woff(1,0,0), conv_Wr + woff(1,0,0), conv_bl + boff(1,0,0), dis_L1_1 };
    GJob jr0 = { ctr + C_DRUG_S0, aggc_drug, a1_drug_s0, emb_drug, l_drug_s0,
                 conv_Wl + woff(0,0,1), conv_Wr + woff(0,0,1), conv_bl + boff(0,0,1), drug_L1_0 };
    GJob jr1 = { ctr + C_DRUG_S1, aggc_drug, a1_drug_s1, emb_drug, l_drug_s1,
                 conv_Wl + woff(1,0,1), conv_Wr + woff(1,0,1), conv_bl + boff(1,0,1), drug_L1_1 };
    k_gemm4<<<NBLK_L1, 256>>>(jd0, jd1, jr0, jr1);
    // 5. L2 gather-mean
    k_gather2<<<dim3(ceildiv(NB * 32, 256), 2), 256>>>(
        l_drug_s0, ctr + C_DRUG_S0, head_drug, next_drug, src_di2dr, s_dis_s0, dis_L1_0, aggc_drug,
        l_dis_s1, ctr + C_DIS_S1, head_dis, next_dis, src_d2di, s_drug_s1, drug_L1_1, aggc_dis);
    // 6. fused L2 GEMMs
    GJob jl0 = { ctr + C_DRUG_S0, aggc_drug, nullptr, drug_L1_0, nullptr,
                 conv_Wl + woff(0,1,1), conv_Wr + woff(0,1,1), conv_bl + boff(0,1,1), drug_L2 };
    GJob jl1 = { ctr + C_DIS_S1,  aggc_dis,  nullptr, dis_L1_1,  nullptr,
                 conv_Wl + woff(1,1,0), conv_Wr + woff(1,1,0), conv_bl + boff(1,1,0), dis_L2 };
    k_gemm2<<<2 * NBLK_NB, 256>>>(jl0, jl1);
    // 7. fold degenerate MHA into MLP layer 1
    k_fold1<<<dim3(128, 2), 128>>>(attn_Win, attn_bin, attn_Wout, attn_bout);
    k_fold2<<<256, 128>>>(mlp_W1, mlp_b1);
    // 8. pair head
    k_gemm<128,256><<<dim3(NBLK_NB, 2), 256>>>(NB, drug_L2, gd, dis_L2, gs,
                                               Md, Ms, btil, H1, 256, 1);
    k_gemm<256,256><<<dim3(NBLK_NB, 1), 256>>>(NB, H1, nullptr, H1, nullptr,
                                               mlp_W2, mlp_W2, mlp_b2, H2, 128, 1);
    k_dot<<<ceildiv(NB * 32, 256), 256>>>(H2, mlp_W3, mlp_b3, out);
}